// round 14
// baseline (speedup 1.0000x reference)
#include <cuda_runtime.h>
#include <cuda_fp16.h>
#include <cstdint>
#include <math.h>

#define SEQ 2048
#define DM  1024
#define NH  16
#define DK  64

// ---------------- scratch (device globals; no allocation allowed) ----------
__device__ float g_sums[NH * SEQ];
__device__ __half g_xq[SEQ * DM], g_xk[SEQ * DM], g_xv[SEQ * DM];
__device__ __half g_wq[DM * DM], g_wk[DM * DM], g_wv[DM * DM], g_wo[DM * DM];
__device__ __half g_Qp[SEQ * DM], g_Kp[SEQ * DM], g_Vp[SEQ * DM];   // proj out
__device__ __half g_Qh[SEQ * DM], g_Kh[SEQ * DM];                    // post-RoPE
__device__ __half g_Vt[NH * DK * SEQ];
__device__ __half g_P[(size_t)NH * SEQ * SEQ];   // fp16 exp(s-8) values
__device__ __half g_ctx[SEQ * DM];

#define L2E 1.442695041f
#define SHFT (-11.541560327f)   /* -8 * log2(e) */

// ---------------------------------------------------------------------------
__device__ __forceinline__ void ldsm4(uint32_t* r, uint32_t a) {
    asm volatile("ldmatrix.sync.aligned.m8n8.x4.shared.b16 {%0,%1,%2,%3}, [%4];"
        : "=r"(r[0]), "=r"(r[1]), "=r"(r[2]), "=r"(r[3]) : "r"(a));
}
__device__ __forceinline__ void mma_f16(float* c, const uint32_t* a,
                                        uint32_t b0, uint32_t b1) {
    asm volatile("mma.sync.aligned.m16n8k16.row.col.f32.f16.f16.f32 "
        "{%0,%1,%2,%3},{%4,%5,%6,%7},{%8,%9},{%0,%1,%2,%3};"
        : "+f"(c[0]), "+f"(c[1]), "+f"(c[2]), "+f"(c[3])
        : "r"(a[0]), "r"(a[1]), "r"(a[2]), "r"(a[3]), "r"(b0), "r"(b1));
}
__device__ __forceinline__ void cp16(uint32_t dst, const void* src) {
    asm volatile("cp.async.cg.shared.global [%0], [%1], 16;" :: "r"(dst), "l"(src));
}
__device__ __forceinline__ void cp_commit() {
    asm volatile("cp.async.commit_group;");
}
template<int N> __device__ __forceinline__ void cp_wait() {
    asm volatile("cp.async.wait_group %0;" :: "n"(N));
}
__device__ __forceinline__ uint32_t swz(int r, int s) {
    return (uint32_t)((r * 4 + ((s + (r >> 1)) & 3)) << 4);
}

// ---------------------------------------------------------------------------
// fp16 NT GEMM body. Block tile 128 x TN (64|128), 8 warps (4M x 2N), BK=32,
// 3-stage cp.async.
// EPI=0: fp32 C (+bias). EPI=1: fp16 Cf (alpha applied);
// EXPS: store fp16(exp(alpha*acc - 8)) and atomicAdd row sums of stored vals.
// ---------------------------------------------------------------------------
template<int TN, int EPI, bool HB, bool EXPS>
__device__ __forceinline__ void gemm_body(
    const __half* __restrict__ A, const __half* __restrict__ B,
    float* __restrict__ C, __half* __restrict__ Cf,
    int K, int lda, int ldb, int ldc, float alpha,
    const float* __restrict__ bias, float* __restrict__ sums,
    int bx, int by)
{
    constexpr int NP = TN / 32;
    constexpr int NJ = TN / 16;
    __shared__ __align__(16) __half As[3][128 * 32];
    __shared__ __align__(16) __half Bs[3][TN * 32];
    constexpr uint32_t ASTR = 128 * 32 * 2, BSTR = TN * 32 * 2;

    const int t = threadIdx.x, lane = t & 31, w = t >> 5;
    const int wm = w & 3, wn = w >> 2;
    const int grp = lane >> 2, qid = lane & 3;

    const uint32_t asb = (uint32_t)__cvta_generic_to_shared(&As[0][0]);
    const uint32_t bsb = (uint32_t)__cvta_generic_to_shared(&Bs[0][0]);

    const int lr = t >> 2, ls = t & 3;
    const __half* pA0 = A + (long long)(by * 128 + lr) * lda + ls * 8;
    const __half* pA1 = pA0 + (long long)64 * lda;
    const __half* pB0 = B + (long long)(bx * TN + lr) * ldb + ls * 8;
    const __half* pB1 = pB0 + (long long)64 * ldb;
    const uint32_t dG0 = swz(lr, ls), dG1 = swz(lr + 64, ls);

    auto load_async = [&](int c, int s) {
        cp16(asb + s * ASTR + dG0, pA0 + c * 32);
        cp16(asb + s * ASTR + dG1, pA1 + c * 32);
        cp16(bsb + s * BSTR + dG0, pB0 + c * 32);
        if (TN == 128) cp16(bsb + s * BSTR + dG1, pB1 + c * 32);
    };

    float acc[2][NJ][4];
#pragma unroll
    for (int i = 0; i < 2; i++)
#pragma unroll
        for (int j = 0; j < NJ; j++)
#pragma unroll
            for (int r = 0; r < 4; r++) acc[i][j][r] = 0.f;

    const int NC = K >> 5;
    load_async(0, 0); cp_commit();
    if (NC > 1) { load_async(1, 1); cp_commit(); }

    int s_cur = 0;
    for (int c = 0; c < NC; ++c) {
        if (c + 1 < NC) cp_wait<1>(); else cp_wait<0>();
        __syncthreads();

        if (c + 2 < NC) {
            int s2 = s_cur + 2; if (s2 >= 3) s2 -= 3;
            load_async(c + 2, s2);
            cp_commit();
        }

        const uint32_t ab = asb + s_cur * ASTR;
        const uint32_t bb = bsb + s_cur * BSTR;
#pragma unroll
        for (int ks = 0; ks < 2; ++ks) {
            uint32_t af[2][4], bf[NP][4];
#pragma unroll
            for (int mt = 0; mt < 2; ++mt) {
                int r = wm * 32 + mt * 16 + (lane & 15);
                int s = 2 * ks + (lane >> 4);
                ldsm4(af[mt], ab + swz(r, s));
            }
#pragma unroll
            for (int p = 0; p < NP; ++p) {
                int r = wn * (TN / 2) + p * 16 + ((lane >> 4) << 3) + (lane & 7);
                int s = 2 * ks + ((lane >> 3) & 1);
                ldsm4(bf[p], bb + swz(r, s));
            }
#pragma unroll
            for (int mt = 0; mt < 2; ++mt)
#pragma unroll
                for (int j = 0; j < NJ; ++j)
                    mma_f16(acc[mt][j], af[mt], bf[j >> 1][2 * (j & 1)],
                            bf[j >> 1][2 * (j & 1) + 1]);
        }

        ++s_cur; if (s_cur == 3) s_cur = 0;
        __syncthreads();
    }

#pragma unroll
    for (int mt = 0; mt < 2; ++mt) {
        int row0 = by * 128 + wm * 32 + mt * 16 + grp;
        float ps0 = 0.f, ps1 = 0.f;
#pragma unroll
        for (int j = 0; j < NJ; ++j) {
            int col = bx * TN + wn * (TN / 2) + j * 8 + 2 * qid;
            if (EPI == 0) {
                float b0 = HB ? bias[col] : 0.f;
                float b1 = HB ? bias[col + 1] : 0.f;
                *(float2*)&C[(long long)row0 * ldc + col] =
                    make_float2(alpha * acc[mt][j][0] + b0, alpha * acc[mt][j][1] + b1);
                *(float2*)&C[(long long)(row0 + 8) * ldc + col] =
                    make_float2(alpha * acc[mt][j][2] + b0, alpha * acc[mt][j][3] + b1);
            } else if (!EXPS) {
                __half2 v0 = __floats2half2_rn(alpha * acc[mt][j][0], alpha * acc[mt][j][1]);
                __half2 v1 = __floats2half2_rn(alpha * acc[mt][j][2], alpha * acc[mt][j][3]);
                *(__half2*)&Cf[(long long)row0 * ldc + col] = v0;
                *(__half2*)&Cf[(long long)(row0 + 8) * ldc + col] = v1;
            } else {
                float e0 = exp2f(fmaf(alpha * acc[mt][j][0], L2E, SHFT));
                float e1 = exp2f(fmaf(alpha * acc[mt][j][1], L2E, SHFT));
                float e2 = exp2f(fmaf(alpha * acc[mt][j][2], L2E, SHFT));
                float e3 = exp2f(fmaf(alpha * acc[mt][j][3], L2E, SHFT));
                __half2 v0 = __floats2half2_rn(e0, e1);
                __half2 v1 = __floats2half2_rn(e2, e3);
                *(__half2*)&Cf[(long long)row0 * ldc + col] = v0;
                *(__half2*)&Cf[(long long)(row0 + 8) * ldc + col] = v1;
                float2 f0 = __half22float2(v0);
                float2 f1 = __half22float2(v1);
                ps0 += f0.x + f0.y;
                ps1 += f1.x + f1.y;
            }
        }
        if (EXPS) {
            ps0 += __shfl_xor_sync(0xffffffffu, ps0, 1);
            ps0 += __shfl_xor_sync(0xffffffffu, ps0, 2);
            ps1 += __shfl_xor_sync(0xffffffffu, ps1, 1);
            ps1 += __shfl_xor_sync(0xffffffffu, ps1, 2);
            if (qid == 0) {
                atomicAdd(&sums[row0], ps0);
                atomicAdd(&sums[row0 + 8], ps1);
            }
        }
    }
}

template<int TN, int EPI, bool HB, bool EXPS>
__global__ __launch_bounds__(256)
void gemm_h(const __half* __restrict__ A, const __half* __restrict__ B,
            float* __restrict__ C, __half* __restrict__ Cf,
            float* __restrict__ sums,
            int K, int lda, int ldb, int ldc, float alpha,
            const float* __restrict__ bias,
            long long sAz, long long sBz, long long sCz)
{
    const __half* Az = A + (long long)blockIdx.z * sAz;
    const __half* Bz = B + (long long)blockIdx.z * sBz;
    float* Cz = C; __half* Cfz = Cf;
    if (EPI == 0) { if (C)  Cz  = C  + (long long)blockIdx.z * sCz; }
    else          { if (Cf) Cfz = Cf + (long long)blockIdx.z * sCz; }
    float* sz = EXPS ? sums + (long long)blockIdx.z * SEQ : nullptr;
    gemm_body<TN, EPI, HB, EXPS>(Az, Bz, Cz, Cfz, K, lda, ldb, ldc, alpha, bias,
                                 sz, blockIdx.x, blockIdx.y);
}

// Scores kernel: TN=64 tile, occupancy-3 target, exp epilogue + row sums.
__global__ __launch_bounds__(256, 3)
void scores_h(const __half* __restrict__ Qh, const __half* __restrict__ Kh,
              __half* __restrict__ P, float* __restrict__ sums)
{
    gemm_body<64, 1, false, true>(
        Qh + blockIdx.z * DK, Kh + blockIdx.z * DK,
        nullptr, P + (long long)blockIdx.z * SEQ * SEQ,
        DK, DM, DM, SEQ, 0.125f, nullptr,
        sums + blockIdx.z * SEQ, blockIdx.x, blockIdx.y);
}

// Fused QKV projection -> fp16 outputs. blockIdx.z selects tensor.
__global__ __launch_bounds__(256)
void gemm_qkv(const __half* __restrict__ xq, const __half* __restrict__ xk,
              const __half* __restrict__ xv,
              const __half* __restrict__ wq, const __half* __restrict__ wk,
              const __half* __restrict__ wv,
              __half* __restrict__ Q, __half* __restrict__ Ko, __half* __restrict__ V)
{
    const __half* A = (blockIdx.z == 0) ? xq : (blockIdx.z == 1) ? xk : xv;
    const __half* B = (blockIdx.z == 0) ? wq : (blockIdx.z == 1) ? wk : wv;
    __half* C = (blockIdx.z == 0) ? Q : (blockIdx.z == 1) ? Ko : V;
    gemm_body<128, 1, false, false>(A, B, nullptr, C, DM, DM, DM, DM, 1.f,
                                    nullptr, nullptr, blockIdx.x, blockIdx.y);
}

// ---------------------------------------------------------------------------
// Fused AV GEMM. P holds fp16 exp values; normalization by 1/sums applied to
// the fp32 attn write (streaming) and to the ctx epilogue.
// ---------------------------------------------------------------------------
__global__ __launch_bounds__(256, 2)
void av_fused(const __half* __restrict__ P, const __half* __restrict__ Vt,
              const float* __restrict__ sums, float* __restrict__ attn,
              __half* __restrict__ ctx)
{
    __shared__ __align__(16) __half Ps[2][128 * 32];
    __shared__ __align__(16) __half Vs[3][64 * 32];
    constexpr uint32_t PSTR = 128 * 32 * 2, VSTR = 64 * 32 * 2;

    const int t = threadIdx.x, lane = t & 31, w = t >> 5;
    const int wm = w & 3, wn = w >> 2, grp = lane >> 2, qid = lane & 3;
    const int h = blockIdx.z, rb = blockIdx.y;

    const int r = t >> 1, hf = t & 1;
    const long long prow = (long long)h * SEQ * SEQ
                         + (long long)(rb * 128 + r) * SEQ + hf * 16;
    const __half* pS = P + prow;
    float* pA = attn + prow;
    const float invr = 1.f / sums[h * SEQ + rb * 128 + r];

    const int lr = t >> 2, ls = t & 3;
    const __half* pV = Vt + (long long)h * DK * SEQ + (long long)lr * SEQ + ls * 8;
    const uint32_t psb = (uint32_t)__cvta_generic_to_shared(&Ps[0][0]);
    const uint32_t vsb = (uint32_t)__cvta_generic_to_shared(&Vs[0][0]);
    const uint32_t dV = swz(lr, ls);
    const uint32_t dP0 = swz(r, 2 * hf), dP1 = swz(r, 2 * hf + 1);

    float acc[2][4][4];
#pragma unroll
    for (int i = 0; i < 2; i++)
#pragma unroll
        for (int j = 0; j < 4; j++)
#pragma unroll
            for (int x = 0; x < 4; x++) acc[i][j][x] = 0.f;

    uint4 sc0, sc1;
    auto ldS = [&](int c) {
        sc0 = *(const uint4*)(pS + c * 32);
        sc1 = *(const uint4*)(pS + c * 32 + 8);
    };
    auto emit = [&](int c, int buf) {
        const __half2* h0 = (const __half2*)&sc0;
        const __half2* h1 = (const __half2*)&sc1;
        float pr[16];
#pragma unroll
        for (int j = 0; j < 4; ++j) {
            float2 f = __half22float2(h0[j]);
            pr[2 * j]     = f.x * invr;
            pr[2 * j + 1] = f.y * invr;
            float2 g = __half22float2(h1[j]);
            pr[8 + 2 * j]     = g.x * invr;
            pr[8 + 2 * j + 1] = g.y * invr;
        }
        float* ap = pA + c * 32;
        __stwt((float4*)(ap),      make_float4(pr[0], pr[1], pr[2], pr[3]));
        __stwt((float4*)(ap + 4),  make_float4(pr[4], pr[5], pr[6], pr[7]));
        __stwt((float4*)(ap + 8),  make_float4(pr[8], pr[9], pr[10], pr[11]));
        __stwt((float4*)(ap + 12), make_float4(pr[12], pr[13], pr[14], pr[15]));
        char* base = (char*)&Ps[buf][0];
        *(uint4*)(base + dP0) = sc0;
        *(uint4*)(base + dP1) = sc1;
    };
    auto cpV = [&](int c, int s) {
        cp16(vsb + s * VSTR + dV, pV + (long long)c * 32);
        cp_commit();
    };

    ldS(0);
    cpV(0, 0); cpV(1, 1);
    emit(0, 0);
    ldS(1);

    for (int c = 0; c < 64; ++c) {
        if (c < 63) cp_wait<1>(); else cp_wait<0>();
        __syncthreads();
        if (c + 2 < 64) cpV(c + 2, (c + 2) % 3);

        const uint32_t pb = psb + (c & 1) * PSTR;
        const uint32_t vb = vsb + (c % 3) * VSTR;
#pragma unroll
        for (int ks = 0; ks < 2; ++ks) {
            uint32_t af[2][4], bf[2][4];
#pragma unroll
            for (int mt = 0; mt < 2; ++mt) {
                int rr = wm * 32 + mt * 16 + (lane & 15);
                int ss = 2 * ks + (lane >> 4);
                ldsm4(af[mt], pb + swz(rr, ss));
            }
#pragma unroll
            for (int p = 0; p < 2; ++p) {
                int rr = wn * 32 + p * 16 + ((lane >> 4) << 3) + (lane & 7);
                int ss = 2 * ks + ((lane >> 3) & 1);
                ldsm4(bf[p], vb + swz(rr, ss));
            }
#pragma unroll
            for (int mt = 0; mt < 2; ++mt)
#pragma unroll
                for (int j = 0; j < 4; ++j)
                    mma_f16(acc[mt][j], af[mt], bf[j >> 1][2 * (j & 1)],
                            bf[j >> 1][2 * (j & 1) + 1]);
        }

        if (c + 1 < 64) {
            emit(c + 1, (c + 1) & 1);
            if (c + 2 < 64) ldS(c + 2);
        }
    }

    // epilogue: ctx = acc * inv[row]
#pragma unroll
    for (int mt = 0; mt < 2; ++mt) {
        int row0 = rb * 128 + wm * 32 + mt * 16 + grp;
        float i0 = 1.f / sums[h * SEQ + row0];
        float i1 = 1.f / sums[h * SEQ + row0 + 8];
#pragma unroll
        for (int j = 0; j < 4; ++j) {
            int col = h * DK + wn * 32 + j * 8 + 2 * qid;
            __half2 v0 = __floats2half2_rn(acc[mt][j][0] * i0, acc[mt][j][1] * i0);
            __half2 v1 = __floats2half2_rn(acc[mt][j][2] * i1, acc[mt][j][3] * i1);
            *(__half2*)&ctx[(long long)row0 * DM + col] = v0;
            *(__half2*)&ctx[(long long)(row0 + 8) * DM + col] = v1;
        }
    }
}

// ---------------------------------------------------------------------------
// Merged fp32 -> fp16 convert for all 7 operand tensors (flattened grid).
// ---------------------------------------------------------------------------
__global__ void cvt_all(const float* __restrict__ q, const float* __restrict__ k,
                        const float* __restrict__ v, const float* __restrict__ wq,
                        const float* __restrict__ wk, const float* __restrict__ wv,
                        const float* __restrict__ wo,
                        __half* __restrict__ xq, __half* __restrict__ xk,
                        __half* __restrict__ xv, __half* __restrict__ hwq,
                        __half* __restrict__ hwk, __half* __restrict__ hwv,
                        __half* __restrict__ hwo)
{
    int b = blockIdx.x;
    const float* src; __half* dst; int idx;
    if (b < 6144) {
        int ti = b >> 11, r = b & 2047;
        src = (ti == 0) ? q : (ti == 1) ? k : v;
        dst = (ti == 0) ? xq : (ti == 1) ? xk : xv;
        idx = r * 256 + threadIdx.x;
    } else {
        int bb = b - 6144;
        int ti = bb >> 10, r = bb & 1023;
        src = (ti == 0) ? wq : (ti == 1) ? wk : (ti == 2) ? wv : wo;
        dst = (ti == 0) ? hwq : (ti == 1) ? hwk : (ti == 2) ? hwv : hwo;
        idx = r * 256 + threadIdx.x;
    }
    float4 x = ((const float4*)src)[idx];
    __half2 u = __floats2half2_rn(x.x, x.y);
    __half2 w2 = __floats2half2_rn(x.z, x.w);
    *(uint2*)(dst + 4 * (size_t)idx) = make_uint2(*(uint32_t*)&u, *(uint32_t*)&w2);
}

// ---------------------------------------------------------------------------
// Merged RoPE (blocks [0,4096)) + V transpose (blocks [4096,6144)), fp16 in.
// ---------------------------------------------------------------------------
__global__ void rope_vtrans(const __half* __restrict__ Qp, const __half* __restrict__ Kp,
                            const __half* __restrict__ Vp,
                            __half* __restrict__ Qh, __half* __restrict__ Kh,
                            __half* __restrict__ Vt)
{
    if (blockIdx.x < 4096) {
        int tid = blockIdx.x * 256 + threadIdx.x;
        int i = tid & 31;
        int h = (tid >> 5) & (NH - 1);
        int s = tid >> 9;

        float inv_freq = exp2f(-0.41524101186092029f * (float)i); // log2(10000)/32
        float angle = (float)s * inv_freq;
        float sn, cs;
        sincosf(angle, &sn, &cs);

        long long base = (long long)s * DM + h * DK + i;
        float q1 = __half2float(Qp[base]), q2 = __half2float(Qp[base + 32]);
        Qh[base]      = __float2half_rn(q1 * cs - q2 * sn);
        Qh[base + 32] = __float2half_rn(q2 * cs + q1 * sn);
        float k1 = __half2float(Kp[base]), k2 = __half2float(Kp[base + 32]);
        Kh[base]      = __float2half_rn(k1 * cs - k2 * sn);
        Kh[base + 32] = __float2half_rn(k2 * cs + k1 * sn);
    } else {
        __shared__ __half tile[32][33];
        int bb = blockIdx.x - 4096;
        int c0 = (bb & 31) * 32, s0 = (bb >> 5) * 32;
        int tx = threadIdx.x & 31, ty = threadIdx.x >> 5;   // 32 x 8
#pragma unroll
        for (int kk = 0; kk < 4; ++kk)
            tile[ty + 8 * kk][tx] = Vp[(long long)(s0 + ty + 8 * kk) * DM + c0 + tx];
        __syncthreads();
#pragma unroll
        for (int kk = 0; kk < 4; ++kk) {
            int c = c0 + ty + 8 * kk;
            int s = s0 + tx;
            long long o = (long long)(c >> 6) * DK * SEQ + (long long)(c & 63) * SEQ + s;
            Vt[o] = tile[tx][ty + 8 * kk];
        }
    }
}

// ---------------------------------------------------------------------------
extern "C" void kernel_launch(void* const* d_in, const int* in_sizes, int n_in,
                              void* d_out, int out_size)
{
    const float* q  = (const float*)d_in[0];
    const float* k  = (const float*)d_in[1];
    const float* v  = (const float*)d_in[2];
    const float* wq = (const float*)d_in[3];
    const float* wk = (const float*)d_in[4];
    const float* wv = (const float*)d_in[5];
    const float* wo = (const float*)d_in[6];
    const float* bo = (const float*)d_in[7];

    float* out  = (float*)d_out;              // [2048, 1024]
    float* attn = out + (size_t)SEQ * DM;     // [16, 2048, 2048]

    float* pSums;
    cudaGetSymbolAddress((void**)&pSums, g_sums);

    __half *xq,*xk,*xv,*hwq,*hwk,*hwv,*hwo,*Qp,*Kp,*Vp,*Qh,*Kh,*Vt,*P,*ctx;
    cudaGetSymbolAddress((void**)&xq, g_xq);
    cudaGetSymbolAddress((void**)&xk, g_xk);
    cudaGetSymbolAddress((void**)&xv, g_xv);
    cudaGetSymbolAddress((void**)&hwq, g_wq);
    cudaGetSymbolAddress((void**)&hwk, g_wk);
    cudaGetSymbolAddress((void**)&hwv, g_wv);
    cudaGetSymbolAddress((void**)&hwo, g_wo);
    cudaGetSymbolAddress((void**)&Qp, g_Qp);
    cudaGetSymbolAddress((void**)&Kp, g_Kp);
    cudaGetSymbolAddress((void**)&Vp, g_Vp);
    cudaGetSymbolAddress((void**)&Qh, g_Qh);
    cudaGetSymbolAddress((void**)&Kh, g_Kh);
    cudaGetSymbolAddress((void**)&Vt, g_Vt);
    cudaGetSymbolAddress((void**)&P, g_P);
    cudaGetSymbolAddress((void**)&ctx, g_ctx);

    // 0) zero row sums + convert all operands to fp16
    cudaMemsetAsync(pSums, 0, NH * SEQ * sizeof(float));
    cvt_all<<<10240, 256>>>(q, k, v, wq, wk, wv, wo,
                            xq, xk, xv, hwq, hwk, hwv, hwo);

    // 1) Fused QKV projections -> fp16 (one launch, 384 CTAs)
    gemm_qkv<<<dim3(DM / 128, SEQ / 128, 3), 256>>>(xq, xk, xv, hwq, hwk, hwv,
                                                    Qp, Kp, Vp);

    // 2) RoPE -> fp16 Q/K ; V transpose -> fp16 Vt (one launch)
    rope_vtrans<<<4096 + 2048, 256>>>(Qp, Kp, Vp, Qh, Kh, Vt);

    // 3) Scores -> fp16 P = exp(QK^T/8 - 8), + row sums (TN=64, occ-3)
    scores_h<<<dim3(SEQ / 64, SEQ / 128, NH), 256>>>(Qh, Kh, P, pSums);

    // 4) Fused AV: attn = P * inv (streamed fp32), ctx = (P@V) * inv (fp16)
    av_fused<<<dim3(1, SEQ / 128, NH), 256>>>(P, Vt, pSums, attn, ctx);

    // 5) out = ctx @ w_o^T + b_o
    dim3 gOut(DM / 128, SEQ / 128, 1);
    gemm_h<128, 0, true, false><<<gOut, 256>>>(ctx, hwo, out, nullptr, nullptr,
                                               DM, DM, DM, DM, 1.f, bo, 0, 0, 0);
}

// round 15
// speedup vs baseline: 1.0329x; 1.0329x over previous
#include <cuda_runtime.h>
#include <cuda_fp16.h>
#include <cstdint>
#include <math.h>

#define SEQ 2048
#define DM  1024
#define NH  16
#define DK  64

// ---------------- scratch (device globals; no allocation allowed) ----------
__device__ float g_sums[NH * SEQ];
__device__ __half g_xq[SEQ * DM], g_xk[SEQ * DM], g_xv[SEQ * DM];
__device__ __half g_wq[DM * DM], g_wk[DM * DM], g_wv[DM * DM], g_wo[DM * DM];
__device__ __half g_Qp[SEQ * DM], g_Kp[SEQ * DM], g_Vp[SEQ * DM];   // proj out
__device__ __half g_Qh[SEQ * DM], g_Kh[SEQ * DM];                    // post-RoPE
__device__ __half g_Vt[NH * DK * SEQ];
__device__ __half g_P[(size_t)NH * SEQ * SEQ];   // fp16 exp(s-8) values
__device__ __half g_ctx[SEQ * DM];

#define L2E 1.442695041f
#define SHFT (-11.541560327f)   /* -8 * log2(e) */

// ---------------------------------------------------------------------------
__device__ __forceinline__ void ldsm4(uint32_t* r, uint32_t a) {
    asm volatile("ldmatrix.sync.aligned.m8n8.x4.shared.b16 {%0,%1,%2,%3}, [%4];"
        : "=r"(r[0]), "=r"(r[1]), "=r"(r[2]), "=r"(r[3]) : "r"(a));
}
__device__ __forceinline__ void stsm4(uint32_t a, uint32_t r0, uint32_t r1,
                                      uint32_t r2, uint32_t r3) {
    asm volatile("stmatrix.sync.aligned.m8n8.x4.shared.b16 [%0], {%1,%2,%3,%4};"
        :: "r"(a), "r"(r0), "r"(r1), "r"(r2), "r"(r3) : "memory");
}
__device__ __forceinline__ void mma_f16(float* c, const uint32_t* a,
                                        uint32_t b0, uint32_t b1) {
    asm volatile("mma.sync.aligned.m16n8k16.row.col.f32.f16.f16.f32 "
        "{%0,%1,%2,%3},{%4,%5,%6,%7},{%8,%9},{%0,%1,%2,%3};"
        : "+f"(c[0]), "+f"(c[1]), "+f"(c[2]), "+f"(c[3])
        : "r"(a[0]), "r"(a[1]), "r"(a[2]), "r"(a[3]), "r"(b0), "r"(b1));
}
__device__ __forceinline__ void cp16(uint32_t dst, const void* src) {
    asm volatile("cp.async.cg.shared.global [%0], [%1], 16;" :: "r"(dst), "l"(src));
}
__device__ __forceinline__ void cp_commit() {
    asm volatile("cp.async.commit_group;");
}
template<int N> __device__ __forceinline__ void cp_wait() {
    asm volatile("cp.async.wait_group %0;" :: "n"(N));
}
__device__ __forceinline__ uint32_t swz(int r, int s) {
    return (uint32_t)((r * 4 + ((s + (r >> 1)) & 3)) << 4);
}

// ---------------------------------------------------------------------------
// fp16 NT GEMM body. Block tile 128 x TN (64|128), 8 warps (4M x 2N), BK=32,
// 3-stage cp.async.
// EPI=0: fp32 C (+bias), direct stores.
// EPI=1: fp16 Cf via stmatrix-staged, row-coalesced stores (alpha applied);
//        EXPS: store fp16(exp(alpha*acc - 8)) and atomicAdd row sums.
// ---------------------------------------------------------------------------
template<int TN, int EPI, bool HB, bool EXPS>
__device__ __forceinline__ void gemm_body(
    const __half* __restrict__ A, const __half* __restrict__ B,
    float* __restrict__ C, __half* __restrict__ Cf,
    int K, int lda, int ldb, int ldc, float alpha,
    const float* __restrict__ bias, float* __restrict__ sums,
    int bx, int by)
{
    constexpr int NP = TN / 32;
    constexpr int NJ = TN / 16;
    constexpr uint32_t ASTR = 128 * 32 * 2, BSTR = TN * 32 * 2;
    __shared__ __align__(16) char SM[3 * ASTR + 3 * BSTR];

    const int t = threadIdx.x, lane = t & 31, w = t >> 5;
    const int wm = w & 3, wn = w >> 2;
    const int grp = lane >> 2, qid = lane & 3;

    const uint32_t asb = (uint32_t)__cvta_generic_to_shared(SM);
    const uint32_t bsb = asb + 3 * ASTR;

    const int lr = t >> 2, ls = t & 3;
    const __half* pA0 = A + (long long)(by * 128 + lr) * lda + ls * 8;
    const __half* pA1 = pA0 + (long long)64 * lda;
    const __half* pB0 = B + (long long)(bx * TN + lr) * ldb + ls * 8;
    const __half* pB1 = pB0 + (long long)64 * ldb;
    const uint32_t dG0 = swz(lr, ls), dG1 = swz(lr + 64, ls);

    auto load_async = [&](int c, int s) {
        cp16(asb + s * ASTR + dG0, pA0 + c * 32);
        cp16(asb + s * ASTR + dG1, pA1 + c * 32);
        cp16(bsb + s * BSTR + dG0, pB0 + c * 32);
        if (TN == 128) cp16(bsb + s * BSTR + dG1, pB1 + c * 32);
    };

    float acc[2][NJ][4];
#pragma unroll
    for (int i = 0; i < 2; i++)
#pragma unroll
        for (int j = 0; j < NJ; j++)
#pragma unroll
            for (int r = 0; r < 4; r++) acc[i][j][r] = 0.f;

    const int NC = K >> 5;
    load_async(0, 0); cp_commit();
    if (NC > 1) { load_async(1, 1); cp_commit(); }

    int s_cur = 0;
    for (int c = 0; c < NC; ++c) {
        if (c + 1 < NC) cp_wait<1>(); else cp_wait<0>();
        __syncthreads();

        if (c + 2 < NC) {
            int s2 = s_cur + 2; if (s2 >= 3) s2 -= 3;
            load_async(c + 2, s2);
            cp_commit();
        }

        const uint32_t ab = asb + s_cur * ASTR;
        const uint32_t bb = bsb + s_cur * BSTR;
#pragma unroll
        for (int ks = 0; ks < 2; ++ks) {
            uint32_t af[2][4], bf[NP][4];
#pragma unroll
            for (int mt = 0; mt < 2; ++mt) {
                int r = wm * 32 + mt * 16 + (lane & 15);
                int s = 2 * ks + (lane >> 4);
                ldsm4(af[mt], ab + swz(r, s));
            }
#pragma unroll
            for (int p = 0; p < NP; ++p) {
                int r = wn * (TN / 2) + p * 16 + ((lane >> 4) << 3) + (lane & 7);
                int s = 2 * ks + ((lane >> 3) & 1);
                ldsm4(bf[p], bb + swz(r, s));
            }
#pragma unroll
            for (int mt = 0; mt < 2; ++mt)
#pragma unroll
                for (int j = 0; j < NJ; ++j)
                    mma_f16(acc[mt][j], af[mt], bf[j >> 1][2 * (j & 1)],
                            bf[j >> 1][2 * (j & 1) + 1]);
        }

        ++s_cur; if (s_cur == 3) s_cur = 0;
        __syncthreads();
    }

    if (EPI == 0) {
#pragma unroll
        for (int mt = 0; mt < 2; ++mt) {
            int row0 = by * 128 + wm * 32 + mt * 16 + grp;
#pragma unroll
            for (int j = 0; j < NJ; ++j) {
                int col = bx * TN + wn * (TN / 2) + j * 8 + 2 * qid;
                float b0 = HB ? bias[col] : 0.f;
                float b1 = HB ? bias[col + 1] : 0.f;
                *(float2*)&C[(long long)row0 * ldc + col] =
                    make_float2(alpha * acc[mt][j][0] + b0, alpha * acc[mt][j][1] + b1);
                *(float2*)&C[(long long)(row0 + 8) * ldc + col] =
                    make_float2(alpha * acc[mt][j][2] + b0, alpha * acc[mt][j][3] + b1);
            }
        }
    } else {
        // ---- staged fp16 epilogue: regs -> stmatrix smem -> coalesced STG ----
        uint32_t vv[2][NJ][2];
#pragma unroll
        for (int mt = 0; mt < 2; ++mt) {
            float ps0 = 0.f, ps1 = 0.f;
#pragma unroll
            for (int j = 0; j < NJ; ++j) {
                float a0 = alpha * acc[mt][j][0], a1 = alpha * acc[mt][j][1];
                float a2 = alpha * acc[mt][j][2], a3 = alpha * acc[mt][j][3];
                __half2 v0, v1;
                if (EXPS) {
                    v0 = __floats2half2_rn(exp2f(fmaf(a0, L2E, SHFT)),
                                           exp2f(fmaf(a1, L2E, SHFT)));
                    v1 = __floats2half2_rn(exp2f(fmaf(a2, L2E, SHFT)),
                                           exp2f(fmaf(a3, L2E, SHFT)));
                    float2 f0 = __half22float2(v0);
                    float2 f1 = __half22float2(v1);
                    ps0 += f0.x + f0.y;
                    ps1 += f1.x + f1.y;
                } else {
                    v0 = __floats2half2_rn(a0, a1);
                    v1 = __floats2half2_rn(a2, a3);
                }
                vv[mt][j][0] = *(uint32_t*)&v0;
                vv[mt][j][1] = *(uint32_t*)&v1;
            }
            if (EXPS) {
                ps0 += __shfl_xor_sync(0xffffffffu, ps0, 1);
                ps0 += __shfl_xor_sync(0xffffffffu, ps0, 2);
                ps1 += __shfl_xor_sync(0xffffffffu, ps1, 1);
                ps1 += __shfl_xor_sync(0xffffffffu, ps1, 2);
                int row0 = by * 128 + wm * 32 + mt * 16 + grp;
                if (qid == 0) {
                    atomicAdd(&sums[row0], ps0);
                    atomicAdd(&sums[row0 + 8], ps1);
                }
            }
        }
        constexpr int PP = TN + 8;   // staging pitch in halfs (conflict-free)
#pragma unroll
        for (int mt = 0; mt < 2; ++mt)
#pragma unroll
            for (int rh = 0; rh < 2; ++rh)
#pragma unroll
                for (int jg = 0; jg < NJ / 4; ++jg) {
                    int srow = wm * 32 + mt * 16 + rh * 8 + (lane & 7);
                    int scol = wn * (TN / 2) + (jg * 4 + (lane >> 3)) * 8;
                    uint32_t addr = asb + (uint32_t)(srow * PP + scol) * 2;
                    stsm4(addr, vv[mt][jg * 4 + 0][rh], vv[mt][jg * 4 + 1][rh],
                          vv[mt][jg * 4 + 2][rh], vv[mt][jg * 4 + 3][rh]);
                }
        __syncthreads();
        const __half* Sst = (const __half*)SM;
#pragma unroll
        for (int rr = 0; rr < 16; ++rr) {
            int row = w * 16 + rr;
            long long go = (long long)(by * 128 + row) * ldc + bx * TN;
            if (TN == 64) {
                uint32_t val = *(const uint32_t*)(Sst + row * PP + lane * 2);
                *(uint32_t*)(Cf + go + lane * 2) = val;
            } else {
                uint2 val = *(const uint2*)(Sst + row * PP + lane * 4);
                *(uint2*)(Cf + go + lane * 4) = val;
            }
        }
    }
}

template<int TN, int EPI, bool HB, bool EXPS>
__global__ __launch_bounds__(256)
void gemm_h(const __half* __restrict__ A, const __half* __restrict__ B,
            float* __restrict__ C, __half* __restrict__ Cf,
            float* __restrict__ sums,
            int K, int lda, int ldb, int ldc, float alpha,
            const float* __restrict__ bias,
            long long sAz, long long sBz, long long sCz)
{
    const __half* Az = A + (long long)blockIdx.z * sAz;
    const __half* Bz = B + (long long)blockIdx.z * sBz;
    float* Cz = C; __half* Cfz = Cf;
    if (EPI == 0) { if (C)  Cz  = C  + (long long)blockIdx.z * sCz; }
    else          { if (Cf) Cfz = Cf + (long long)blockIdx.z * sCz; }
    float* sz = EXPS ? sums + (long long)blockIdx.z * SEQ : nullptr;
    gemm_body<TN, EPI, HB, EXPS>(Az, Bz, Cz, Cfz, K, lda, ldb, ldc, alpha, bias,
                                 sz, blockIdx.x, blockIdx.y);
}

// Scores kernel: TN=64 tile, occupancy-3 target, exp epilogue + row sums.
__global__ __launch_bounds__(256, 3)
void scores_h(const __half* __restrict__ Qh, const __half* __restrict__ Kh,
              __half* __restrict__ P, float* __restrict__ sums)
{
    gemm_body<64, 1, false, true>(
        Qh + blockIdx.z * DK, Kh + blockIdx.z * DK,
        nullptr, P + (long long)blockIdx.z * SEQ * SEQ,
        DK, DM, DM, SEQ, 0.125f, nullptr,
        sums + blockIdx.z * SEQ, blockIdx.x, blockIdx.y);
}

// Fused QKV projection -> fp16 outputs. blockIdx.z selects tensor.
__global__ __launch_bounds__(256)
void gemm_qkv(const __half* __restrict__ xq, const __half* __restrict__ xk,
              const __half* __restrict__ xv,
              const __half* __restrict__ wq, const __half* __restrict__ wk,
              const __half* __restrict__ wv,
              __half* __restrict__ Q, __half* __restrict__ Ko, __half* __restrict__ V)
{
    const __half* A = (blockIdx.z == 0) ? xq : (blockIdx.z == 1) ? xk : xv;
    const __half* B = (blockIdx.z == 0) ? wq : (blockIdx.z == 1) ? wk : wv;
    __half* C = (blockIdx.z == 0) ? Q : (blockIdx.z == 1) ? Ko : V;
    gemm_body<128, 1, false, false>(A, B, nullptr, C, DM, DM, DM, DM, 1.f,
                                    nullptr, nullptr, blockIdx.x, blockIdx.y);
}

// ---------------------------------------------------------------------------
// Fused AV GEMM. P holds fp16 exp values; normalization by 1/sums applied to
// the fp32 attn write (streaming) and to the ctx epilogue.
// ---------------------------------------------------------------------------
__global__ __launch_bounds__(256, 2)
void av_fused(const __half* __restrict__ P, const __half* __restrict__ Vt,
              const float* __restrict__ sums, float* __restrict__ attn,
              __half* __restrict__ ctx)
{
    __shared__ __align__(16) __half Ps[2][128 * 32];
    __shared__ __align__(16) __half Vs[3][64 * 32];
    constexpr uint32_t PSTR = 128 * 32 * 2, VSTR = 64 * 32 * 2;

    const int t = threadIdx.x, lane = t & 31, w = t >> 5;
    const int wm = w & 3, wn = w >> 2, grp = lane >> 2, qid = lane & 3;
    const int h = blockIdx.z, rb = blockIdx.y;

    const int r = t >> 1, hf = t & 1;
    const long long prow = (long long)h * SEQ * SEQ
                         + (long long)(rb * 128 + r) * SEQ + hf * 16;
    const __half* pS = P + prow;
    float* pA = attn + prow;
    const float invr = 1.f / sums[h * SEQ + rb * 128 + r];

    const int lr = t >> 2, ls = t & 3;
    const __half* pV = Vt + (long long)h * DK * SEQ + (long long)lr * SEQ + ls * 8;
    const uint32_t psb = (uint32_t)__cvta_generic_to_shared(&Ps[0][0]);
    const uint32_t vsb = (uint32_t)__cvta_generic_to_shared(&Vs[0][0]);
    const uint32_t dV = swz(lr, ls);
    const uint32_t dP0 = swz(r, 2 * hf), dP1 = swz(r, 2 * hf + 1);

    float acc[2][4][4];
#pragma unroll
    for (int i = 0; i < 2; i++)
#pragma unroll
        for (int j = 0; j < 4; j++)
#pragma unroll
            for (int x = 0; x < 4; x++) acc[i][j][x] = 0.f;

    uint4 sc0, sc1;
    auto ldS = [&](int c) {
        sc0 = *(const uint4*)(pS + c * 32);
        sc1 = *(const uint4*)(pS + c * 32 + 8);
    };
    auto emit = [&](int c, int buf) {
        const __half2* h0 = (const __half2*)&sc0;
        const __half2* h1 = (const __half2*)&sc1;
        float pr[16];
#pragma unroll
        for (int j = 0; j < 4; ++j) {
            float2 f = __half22float2(h0[j]);
            pr[2 * j]     = f.x * invr;
            pr[2 * j + 1] = f.y * invr;
            float2 g = __half22float2(h1[j]);
            pr[8 + 2 * j]     = g.x * invr;
            pr[8 + 2 * j + 1] = g.y * invr;
        }
        float* ap = pA + c * 32;
        __stwt((float4*)(ap),      make_float4(pr[0], pr[1], pr[2], pr[3]));
        __stwt((float4*)(ap + 4),  make_float4(pr[4], pr[5], pr[6], pr[7]));
        __stwt((float4*)(ap + 8),  make_float4(pr[8], pr[9], pr[10], pr[11]));
        __stwt((float4*)(ap + 12), make_float4(pr[12], pr[13], pr[14], pr[15]));
        char* base = (char*)&Ps[buf][0];
        *(uint4*)(base + dP0) = sc0;
        *(uint4*)(base + dP1) = sc1;
    };
    auto cpV = [&](int c, int s) {
        cp16(vsb + s * VSTR + dV, pV + (long long)c * 32);
        cp_commit();
    };

    ldS(0);
    cpV(0, 0); cpV(1, 1);
    emit(0, 0);
    ldS(1);

    for (int c = 0; c < 64; ++c) {
        if (c < 63) cp_wait<1>(); else cp_wait<0>();
        __syncthreads();
        if (c + 2 < 64) cpV(c + 2, (c + 2) % 3);

        const uint32_t pb = psb + (c & 1) * PSTR;
        const uint32_t vb = vsb + (c % 3) * VSTR;
#pragma unroll
        for (int ks = 0; ks < 2; ++ks) {
            uint32_t af[2][4], bf[2][4];
#pragma unroll
            for (int mt = 0; mt < 2; ++mt) {
                int rr = wm * 32 + mt * 16 + (lane & 15);
                int ss = 2 * ks + (lane >> 4);
                ldsm4(af[mt], pb + swz(rr, ss));
            }
#pragma unroll
            for (int p = 0; p < 2; ++p) {
                int rr = wn * 32 + p * 16 + ((lane >> 4) << 3) + (lane & 7);
                int ss = 2 * ks + ((lane >> 3) & 1);
                ldsm4(bf[p], vb + swz(rr, ss));
            }
#pragma unroll
            for (int mt = 0; mt < 2; ++mt)
#pragma unroll
                for (int j = 0; j < 4; ++j)
                    mma_f16(acc[mt][j], af[mt], bf[j >> 1][2 * (j & 1)],
                            bf[j >> 1][2 * (j & 1) + 1]);
        }

        if (c + 1 < 64) {
            emit(c + 1, (c + 1) & 1);
            if (c + 2 < 64) ldS(c + 2);
        }
    }

    // epilogue: ctx = acc * inv[row]
#pragma unroll
    for (int mt = 0; mt < 2; ++mt) {
        int row0 = rb * 128 + wm * 32 + mt * 16 + grp;
        float i0 = 1.f / sums[h * SEQ + row0];
        float i1 = 1.f / sums[h * SEQ + row0 + 8];
#pragma unroll
        for (int j = 0; j < 4; ++j) {
            int col = h * DK + wn * 32 + j * 8 + 2 * qid;
            __half2 v0 = __floats2half2_rn(acc[mt][j][0] * i0, acc[mt][j][1] * i0);
            __half2 v1 = __floats2half2_rn(acc[mt][j][2] * i1, acc[mt][j][3] * i1);
            *(__half2*)&ctx[(long long)row0 * DM + col] = v0;
            *(__half2*)&ctx[(long long)(row0 + 8) * DM + col] = v1;
        }
    }
}

// ---------------------------------------------------------------------------
// Merged fp32 -> fp16 convert for all 7 operand tensors (flattened grid).
// ---------------------------------------------------------------------------
__global__ void cvt_all(const float* __restrict__ q, const float* __restrict__ k,
                        const float* __restrict__ v, const float* __restrict__ wq,
                        const float* __restrict__ wk, const float* __restrict__ wv,
                        const float* __restrict__ wo,
                        __half* __restrict__ xq, __half* __restrict__ xk,
                        __half* __restrict__ xv, __half* __restrict__ hwq,
                        __half* __restrict__ hwk, __half* __restrict__ hwv,
                        __half* __restrict__ hwo)
{
    int b = blockIdx.x;
    const float* src; __half* dst; int idx;
    if (b < 6144) {
        int ti = b >> 11, r = b & 2047;
        src = (ti == 0) ? q : (ti == 1) ? k : v;
        dst = (ti == 0) ? xq : (ti == 1) ? xk : xv;
        idx = r * 256 + threadIdx.x;
    } else {
        int bb = b - 6144;
        int ti = bb >> 10, r = bb & 1023;
        src = (ti == 0) ? wq : (ti == 1) ? wk : (ti == 2) ? wv : wo;
        dst = (ti == 0) ? hwq : (ti == 1) ? hwk : (ti == 2) ? hwv : hwo;
        idx = r * 256 + threadIdx.x;
    }
    float4 x = ((const float4*)src)[idx];
    __half2 u = __floats2half2_rn(x.x, x.y);
    __half2 w2 = __floats2half2_rn(x.z, x.w);
    *(uint2*)(dst + 4 * (size_t)idx) = make_uint2(*(uint32_t*)&u, *(uint32_t*)&w2);
}

// ---------------------------------------------------------------------------
// Merged RoPE (blocks [0,4096)) + V transpose (blocks [4096,6144)), fp16 in.
// ---------------------------------------------------------------------------
__global__ void rope_vtrans(const __half* __restrict__ Qp, const __half* __restrict__ Kp,
                            const __half* __restrict__ Vp,
                            __half* __restrict__ Qh, __half* __restrict__ Kh,
                            __half* __restrict__ Vt)
{
    if (blockIdx.x < 4096) {
        int tid = blockIdx.x * 256 + threadIdx.x;
        int i = tid & 31;
        int h = (tid >> 5) & (NH - 1);
        int s = tid >> 9;

        float inv_freq = exp2f(-0.41524101186092029f * (float)i); // log2(10000)/32
        float angle = (float)s * inv_freq;
        float sn, cs;
        sincosf(angle, &sn, &cs);

        long long base = (long long)s * DM + h * DK + i;
        float q1 = __half2float(Qp[base]), q2 = __half2float(Qp[base + 32]);
        Qh[base]      = __float2half_rn(q1 * cs - q2 * sn);
        Qh[base + 32] = __float2half_rn(q2 * cs + q1 * sn);
        float k1 = __half2float(Kp[base]), k2 = __half2float(Kp[base + 32]);
        Kh[base]      = __float2half_rn(k1 * cs - k2 * sn);
        Kh[base + 32] = __float2half_rn(k2 * cs + k1 * sn);
    } else {
        __shared__ __half tile[32][33];
        int bb = blockIdx.x - 4096;
        int c0 = (bb & 31) * 32, s0 = (bb >> 5) * 32;
        int tx = threadIdx.x & 31, ty = threadIdx.x >> 5;   // 32 x 8
#pragma unroll
        for (int kk = 0; kk < 4; ++kk)
            tile[ty + 8 * kk][tx] = Vp[(long long)(s0 + ty + 8 * kk) * DM + c0 + tx];
        __syncthreads();
#pragma unroll
        for (int kk = 0; kk < 4; ++kk) {
            int c = c0 + ty + 8 * kk;
            int s = s0 + tx;
            long long o = (long long)(c >> 6) * DK * SEQ + (long long)(c & 63) * SEQ + s;
            Vt[o] = tile[tx][ty + 8 * kk];
        }
    }
}

// ---------------------------------------------------------------------------
extern "C" void kernel_launch(void* const* d_in, const int* in_sizes, int n_in,
                              void* d_out, int out_size)
{
    const float* q  = (const float*)d_in[0];
    const float* k  = (const float*)d_in[1];
    const float* v  = (const float*)d_in[2];
    const float* wq = (const float*)d_in[3];
    const float* wk = (const float*)d_in[4];
    const float* wv = (const float*)d_in[5];
    const float* wo = (const float*)d_in[6];
    const float* bo = (const float*)d_in[7];

    float* out  = (float*)d_out;              // [2048, 1024]
    float* attn = out + (size_t)SEQ * DM;     // [16, 2048, 2048]

    float* pSums;
    cudaGetSymbolAddress((void**)&pSums, g_sums);

    __half *xq,*xk,*xv,*hwq,*hwk,*hwv,*hwo,*Qp,*Kp,*Vp,*Qh,*Kh,*Vt,*P,*ctx;
    cudaGetSymbolAddress((void**)&xq, g_xq);
    cudaGetSymbolAddress((void**)&xk, g_xk);
    cudaGetSymbolAddress((void**)&xv, g_xv);
    cudaGetSymbolAddress((void**)&hwq, g_wq);
    cudaGetSymbolAddress((void**)&hwk, g_wk);
    cudaGetSymbolAddress((void**)&hwv, g_wv);
    cudaGetSymbolAddress((void**)&hwo, g_wo);
    cudaGetSymbolAddress((void**)&Qp, g_Qp);
    cudaGetSymbolAddress((void**)&Kp, g_Kp);
    cudaGetSymbolAddress((void**)&Vp, g_Vp);
    cudaGetSymbolAddress((void**)&Qh, g_Qh);
    cudaGetSymbolAddress((void**)&Kh, g_Kh);
    cudaGetSymbolAddress((void**)&Vt, g_Vt);
    cudaGetSymbolAddress((void**)&P, g_P);
    cudaGetSymbolAddress((void**)&ctx, g_ctx);

    // 0) zero row sums + convert all operands to fp16
    cudaMemsetAsync(pSums, 0, NH * SEQ * sizeof(float));
    cvt_all<<<10240, 256>>>(q, k, v, wq, wk, wv, wo,
                            xq, xk, xv, hwq, hwk, hwv, hwo);

    // 1) Fused QKV projections -> fp16 (one launch, 384 CTAs)
    gemm_qkv<<<dim3(DM / 128, SEQ / 128, 3), 256>>>(xq, xk, xv, hwq, hwk, hwv,
                                                    Qp, Kp, Vp);

    // 2) RoPE -> fp16 Q/K ; V transpose -> fp16 Vt (one launch)
    rope_vtrans<<<4096 + 2048, 256>>>(Qp, Kp, Vp, Qh, Kh, Vt);

    // 3) Scores -> fp16 P = exp(QK^T/8 - 8), + row sums (TN=64, occ-3)
    scores_h<<<dim3(SEQ / 64, SEQ / 128, NH), 256>>>(Qh, Kh, P, pSums);

    // 4) Fused AV: attn = P * inv (streamed fp32), ctx = (P@V) * inv (fp16)
    av_fused<<<dim3(1, SEQ / 128, NH), 256>>>(P, Vt, pSums, attn, ctx);

    // 5) out = ctx @ w_o^T + b_o
    dim3 gOut(DM / 128, SEQ / 128, 1);
    gemm_h<128, 0, true, false><<<gOut, 256>>>(ctx, hwo, out, nullptr, nullptr,
                                               DM, DM, DM, DM, 1.f, bo, 0, 0, 0);
}

// round 16
// speedup vs baseline: 1.0407x; 1.0076x over previous
#include <cuda_runtime.h>
#include <cuda_fp16.h>
#include <cstdint>
#include <math.h>

#define SEQ 2048
#define DM  1024
#define NH  16
#define DK  64

// ---------------- scratch (device globals; no allocation allowed) ----------
__device__ float g_sums[NH * SEQ];
__device__ __half g_xq[SEQ * DM], g_xk[SEQ * DM], g_xv[SEQ * DM];
__device__ __half g_wq[DM * DM], g_wk[DM * DM], g_wv[DM * DM], g_wo[DM * DM];
__device__ __half g_Qp[SEQ * DM], g_Kp[SEQ * DM], g_Vp[SEQ * DM];   // proj out
__device__ __half g_Qh[SEQ * DM], g_Kh[SEQ * DM];                    // post-RoPE
__device__ __half g_Vt[NH * DK * SEQ];
__device__ __half g_P[(size_t)NH * SEQ * SEQ];   // fp16 exp(s-8) values
__device__ __half g_ctx[SEQ * DM];

#define L2E 1.442695041f
#define SHFT (-11.541560327f)   /* -8 * log2(e) */

// ---------------------------------------------------------------------------
__device__ __forceinline__ void ldsm4(uint32_t* r, uint32_t a) {
    asm volatile("ldmatrix.sync.aligned.m8n8.x4.shared.b16 {%0,%1,%2,%3}, [%4];"
        : "=r"(r[0]), "=r"(r[1]), "=r"(r[2]), "=r"(r[3]) : "r"(a));
}
__device__ __forceinline__ void stsm4(uint32_t a, uint32_t r0, uint32_t r1,
                                      uint32_t r2, uint32_t r3) {
    asm volatile("stmatrix.sync.aligned.m8n8.x4.shared.b16 [%0], {%1,%2,%3,%4};"
        :: "r"(a), "r"(r0), "r"(r1), "r"(r2), "r"(r3) : "memory");
}
__device__ __forceinline__ void mma_f16(float* c, const uint32_t* a,
                                        uint32_t b0, uint32_t b1) {
    asm volatile("mma.sync.aligned.m16n8k16.row.col.f32.f16.f16.f32 "
        "{%0,%1,%2,%3},{%4,%5,%6,%7},{%8,%9},{%0,%1,%2,%3};"
        : "+f"(c[0]), "+f"(c[1]), "+f"(c[2]), "+f"(c[3])
        : "r"(a[0]), "r"(a[1]), "r"(a[2]), "r"(a[3]), "r"(b0), "r"(b1));
}
__device__ __forceinline__ void cp16(uint32_t dst, const void* src) {
    asm volatile("cp.async.cg.shared.global [%0], [%1], 16;" :: "r"(dst), "l"(src));
}
__device__ __forceinline__ void cp_commit() {
    asm volatile("cp.async.commit_group;");
}
template<int N> __device__ __forceinline__ void cp_wait() {
    asm volatile("cp.async.wait_group %0;" :: "n"(N));
}
__device__ __forceinline__ uint32_t swz(int r, int s) {
    return (uint32_t)((r * 4 + ((s + (r >> 1)) & 3)) << 4);
}

// ---------------------------------------------------------------------------
// fp16 NT GEMM body. Block tile 128 x TN (64|128), 8 warps (4M x 2N), BK=32,
// 3-stage cp.async.
// EPI=0: fp32 C (+bias), direct stores.
// EPI=1: fp16 Cf via stmatrix-staged, row-coalesced stores (alpha applied);
//        EXPS: store fp16(exp(alpha*acc - 8)) and atomicAdd row sums.
// ---------------------------------------------------------------------------
template<int TN, int EPI, bool HB, bool EXPS>
__device__ __forceinline__ void gemm_body(
    const __half* __restrict__ A, const __half* __restrict__ B,
    float* __restrict__ C, __half* __restrict__ Cf,
    int K, int lda, int ldb, int ldc, float alpha,
    const float* __restrict__ bias, float* __restrict__ sums,
    int bx, int by)
{
    constexpr int NP = TN / 32;
    constexpr int NJ = TN / 16;
    constexpr uint32_t ASTR = 128 * 32 * 2, BSTR = TN * 32 * 2;
    __shared__ __align__(16) char SM[3 * ASTR + 3 * BSTR];

    const int t = threadIdx.x, lane = t & 31, w = t >> 5;
    const int wm = w & 3, wn = w >> 2;
    const int grp = lane >> 2, qid = lane & 3;

    const uint32_t asb = (uint32_t)__cvta_generic_to_shared(SM);
    const uint32_t bsb = asb + 3 * ASTR;

    const int lr = t >> 2, ls = t & 3;
    const __half* pA0 = A + (long long)(by * 128 + lr) * lda + ls * 8;
    const __half* pA1 = pA0 + (long long)64 * lda;
    const __half* pB0 = B + (long long)(bx * TN + lr) * ldb + ls * 8;
    const __half* pB1 = pB0 + (long long)64 * ldb;
    const uint32_t dG0 = swz(lr, ls), dG1 = swz(lr + 64, ls);

    auto load_async = [&](int c, int s) {
        cp16(asb + s * ASTR + dG0, pA0 + c * 32);
        cp16(asb + s * ASTR + dG1, pA1 + c * 32);
        cp16(bsb + s * BSTR + dG0, pB0 + c * 32);
        if (TN == 128) cp16(bsb + s * BSTR + dG1, pB1 + c * 32);
    };

    float acc[2][NJ][4];
#pragma unroll
    for (int i = 0; i < 2; i++)
#pragma unroll
        for (int j = 0; j < NJ; j++)
#pragma unroll
            for (int r = 0; r < 4; r++) acc[i][j][r] = 0.f;

    const int NC = K >> 5;
    load_async(0, 0); cp_commit();
    if (NC > 1) { load_async(1, 1); cp_commit(); }

    int s_cur = 0;
    for (int c = 0; c < NC; ++c) {
        if (c + 1 < NC) cp_wait<1>(); else cp_wait<0>();
        __syncthreads();

        if (c + 2 < NC) {
            int s2 = s_cur + 2; if (s2 >= 3) s2 -= 3;
            load_async(c + 2, s2);
            cp_commit();
        }

        const uint32_t ab = asb + s_cur * ASTR;
        const uint32_t bb = bsb + s_cur * BSTR;
#pragma unroll
        for (int ks = 0; ks < 2; ++ks) {
            uint32_t af[2][4], bf[NP][4];
#pragma unroll
            for (int mt = 0; mt < 2; ++mt) {
                int r = wm * 32 + mt * 16 + (lane & 15);
                int s = 2 * ks + (lane >> 4);
                ldsm4(af[mt], ab + swz(r, s));
            }
#pragma unroll
            for (int p = 0; p < NP; ++p) {
                int r = wn * (TN / 2) + p * 16 + ((lane >> 4) << 3) + (lane & 7);
                int s = 2 * ks + ((lane >> 3) & 1);
                ldsm4(bf[p], bb + swz(r, s));
            }
#pragma unroll
            for (int mt = 0; mt < 2; ++mt)
#pragma unroll
                for (int j = 0; j < NJ; ++j)
                    mma_f16(acc[mt][j], af[mt], bf[j >> 1][2 * (j & 1)],
                            bf[j >> 1][2 * (j & 1) + 1]);
        }

        ++s_cur; if (s_cur == 3) s_cur = 0;
        __syncthreads();
    }

    if (EPI == 0) {
#pragma unroll
        for (int mt = 0; mt < 2; ++mt) {
            int row0 = by * 128 + wm * 32 + mt * 16 + grp;
#pragma unroll
            for (int j = 0; j < NJ; ++j) {
                int col = bx * TN + wn * (TN / 2) + j * 8 + 2 * qid;
                float b0 = HB ? bias[col] : 0.f;
                float b1 = HB ? bias[col + 1] : 0.f;
                *(float2*)&C[(long long)row0 * ldc + col] =
                    make_float2(alpha * acc[mt][j][0] + b0, alpha * acc[mt][j][1] + b1);
                *(float2*)&C[(long long)(row0 + 8) * ldc + col] =
                    make_float2(alpha * acc[mt][j][2] + b0, alpha * acc[mt][j][3] + b1);
            }
        }
    } else {
        uint32_t vv[2][NJ][2];
#pragma unroll
        for (int mt = 0; mt < 2; ++mt) {
            float ps0 = 0.f, ps1 = 0.f;
#pragma unroll
            for (int j = 0; j < NJ; ++j) {
                float a0 = alpha * acc[mt][j][0], a1 = alpha * acc[mt][j][1];
                float a2 = alpha * acc[mt][j][2], a3 = alpha * acc[mt][j][3];
                __half2 v0, v1;
                if (EXPS) {
                    v0 = __floats2half2_rn(exp2f(fmaf(a0, L2E, SHFT)),
                                           exp2f(fmaf(a1, L2E, SHFT)));
                    v1 = __floats2half2_rn(exp2f(fmaf(a2, L2E, SHFT)),
                                           exp2f(fmaf(a3, L2E, SHFT)));
                    float2 f0 = __half22float2(v0);
                    float2 f1 = __half22float2(v1);
                    ps0 += f0.x + f0.y;
                    ps1 += f1.x + f1.y;
                } else {
                    v0 = __floats2half2_rn(a0, a1);
                    v1 = __floats2half2_rn(a2, a3);
                }
                vv[mt][j][0] = *(uint32_t*)&v0;
                vv[mt][j][1] = *(uint32_t*)&v1;
            }
            if (EXPS) {
                ps0 += __shfl_xor_sync(0xffffffffu, ps0, 1);
                ps0 += __shfl_xor_sync(0xffffffffu, ps0, 2);
                ps1 += __shfl_xor_sync(0xffffffffu, ps1, 1);
                ps1 += __shfl_xor_sync(0xffffffffu, ps1, 2);
                int row0 = by * 128 + wm * 32 + mt * 16 + grp;
                if (qid == 0) {
                    atomicAdd(&sums[row0], ps0);
                    atomicAdd(&sums[row0 + 8], ps1);
                }
            }
        }
        constexpr int PP = TN + 8;
#pragma unroll
        for (int mt = 0; mt < 2; ++mt)
#pragma unroll
            for (int rh = 0; rh < 2; ++rh)
#pragma unroll
                for (int jg = 0; jg < NJ / 4; ++jg) {
                    int srow = wm * 32 + mt * 16 + rh * 8 + (lane & 7);
                    int scol = wn * (TN / 2) + (jg * 4 + (lane >> 3)) * 8;
                    uint32_t addr = asb + (uint32_t)(srow * PP + scol) * 2;
                    stsm4(addr, vv[mt][jg * 4 + 0][rh], vv[mt][jg * 4 + 1][rh],
                          vv[mt][jg * 4 + 2][rh], vv[mt][jg * 4 + 3][rh]);
                }
        __syncthreads();
        const __half* Sst = (const __half*)SM;
#pragma unroll
        for (int rr = 0; rr < 16; ++rr) {
            int row = w * 16 + rr;
            long long go = (long long)(by * 128 + row) * ldc + bx * TN;
            if (TN == 64) {
                uint32_t val = *(const uint32_t*)(Sst + row * PP + lane * 2);
                *(uint32_t*)(Cf + go + lane * 2) = val;
            } else {
                uint2 val = *(const uint2*)(Sst + row * PP + lane * 4);
                *(uint2*)(Cf + go + lane * 4) = val;
            }
        }
    }
}

template<int TN, int EPI, bool HB, bool EXPS>
__global__ __launch_bounds__(256)
void gemm_h(const __half* __restrict__ A, const __half* __restrict__ B,
            float* __restrict__ C, __half* __restrict__ Cf,
            float* __restrict__ sums,
            int K, int lda, int ldb, int ldc, float alpha,
            const float* __restrict__ bias,
            long long sAz, long long sBz, long long sCz)
{
    const __half* Az = A + (long long)blockIdx.z * sAz;
    const __half* Bz = B + (long long)blockIdx.z * sBz;
    float* Cz = C; __half* Cfz = Cf;
    if (EPI == 0) { if (C)  Cz  = C  + (long long)blockIdx.z * sCz; }
    else          { if (Cf) Cfz = Cf + (long long)blockIdx.z * sCz; }
    float* sz = EXPS ? sums + (long long)blockIdx.z * SEQ : nullptr;
    gemm_body<TN, EPI, HB, EXPS>(Az, Bz, Cz, Cfz, K, lda, ldb, ldc, alpha, bias,
                                 sz, blockIdx.x, blockIdx.y);
}

// ---------------------------------------------------------------------------
// Dedicated scores kernel: single-shot K=64 (one cp.async burst, one sync),
// 128x64 tile, exp epilogue + row sums + staged coalesced stores. occ-3.
// 128B rows in smem, swizzle: byte = r*128 + (s ^ (r&7))*16.
// ---------------------------------------------------------------------------
__global__ __launch_bounds__(256, 3)
void scores_h(const __half* __restrict__ Qh, const __half* __restrict__ Kh,
              __half* __restrict__ P, float* __restrict__ sums)
{
    __shared__ __align__(16) char SM[(128 + 64) * 128];   // A 16KB + B 8KB
    const int t = threadIdx.x, lane = t & 31, w = t >> 5;
    const int wm = w & 3, wn = w >> 2, grp = lane >> 2, qid = lane & 3;
    const int bx = blockIdx.x, by = blockIdx.y, h = blockIdx.z;

    const uint32_t asb = (uint32_t)__cvta_generic_to_shared(SM);
    const uint32_t bsb = asb + 128 * 128;

    const __half* Qz = Qh + h * DK;
    const __half* Kz = Kh + h * DK;

    // load A: 1024 granules (r=idx>>3, s=idx&7); B: 512 granules
#pragma unroll
    for (int i = 0; i < 4; ++i) {
        int idx = t + i * 256;
        int r = idx >> 3, s = idx & 7;
        cp16(asb + (uint32_t)(r * 128 + ((s ^ (r & 7)) << 4)),
             Qz + (long long)(by * 128 + r) * DM + s * 8);
    }
#pragma unroll
    for (int i = 0; i < 2; ++i) {
        int idx = t + i * 256;
        int r = idx >> 3, s = idx & 7;
        cp16(bsb + (uint32_t)(r * 128 + ((s ^ (r & 7)) << 4)),
             Kz + (long long)(bx * 64 + r) * DM + s * 8);
    }
    cp_commit();
    cp_wait<0>();
    __syncthreads();

    float acc[2][4][4];
#pragma unroll
    for (int i = 0; i < 2; i++)
#pragma unroll
        for (int j = 0; j < 4; j++)
#pragma unroll
            for (int r = 0; r < 4; r++) acc[i][j][r] = 0.f;

#pragma unroll
    for (int ks = 0; ks < 4; ++ks) {
        uint32_t af[2][4], bf[2][4];
#pragma unroll
        for (int mt = 0; mt < 2; ++mt) {
            int r = wm * 32 + mt * 16 + (lane & 15);
            int s = 2 * ks + (lane >> 4);
            ldsm4(af[mt], asb + (uint32_t)(r * 128 + ((s ^ (r & 7)) << 4)));
        }
#pragma unroll
        for (int p = 0; p < 2; ++p) {
            int r = wn * 32 + p * 16 + ((lane >> 4) << 3) + (lane & 7);
            int s = 2 * ks + ((lane >> 3) & 1);
            ldsm4(bf[p], bsb + (uint32_t)(r * 128 + ((s ^ (r & 7)) << 4)));
        }
#pragma unroll
        for (int mt = 0; mt < 2; ++mt)
#pragma unroll
            for (int j = 0; j < 4; ++j)
                mma_f16(acc[mt][j], af[mt], bf[j >> 1][2 * (j & 1)],
                        bf[j >> 1][2 * (j & 1) + 1]);
    }
    __syncthreads();

    // ---- exp epilogue + row sums + staged stores ----
    float* sz = sums + h * SEQ;
    __half* Pz = P + (long long)h * SEQ * SEQ;
    uint32_t vv[2][4][2];
#pragma unroll
    for (int mt = 0; mt < 2; ++mt) {
        float ps0 = 0.f, ps1 = 0.f;
#pragma unroll
        for (int j = 0; j < 4; ++j) {
            float a0 = 0.125f * acc[mt][j][0], a1 = 0.125f * acc[mt][j][1];
            float a2 = 0.125f * acc[mt][j][2], a3 = 0.125f * acc[mt][j][3];
            __half2 v0 = __floats2half2_rn(exp2f(fmaf(a0, L2E, SHFT)),
                                           exp2f(fmaf(a1, L2E, SHFT)));
            __half2 v1 = __floats2half2_rn(exp2f(fmaf(a2, L2E, SHFT)),
                                           exp2f(fmaf(a3, L2E, SHFT)));
            float2 f0 = __half22float2(v0);
            float2 f1 = __half22float2(v1);
            ps0 += f0.x + f0.y;
            ps1 += f1.x + f1.y;
            vv[mt][j][0] = *(uint32_t*)&v0;
            vv[mt][j][1] = *(uint32_t*)&v1;
        }
        ps0 += __shfl_xor_sync(0xffffffffu, ps0, 1);
        ps0 += __shfl_xor_sync(0xffffffffu, ps0, 2);
        ps1 += __shfl_xor_sync(0xffffffffu, ps1, 1);
        ps1 += __shfl_xor_sync(0xffffffffu, ps1, 2);
        int row0 = by * 128 + wm * 32 + mt * 16 + grp;
        if (qid == 0) {
            atomicAdd(&sz[row0], ps0);
            atomicAdd(&sz[row0 + 8], ps1);
        }
    }
    constexpr int PP = 72;
#pragma unroll
    for (int mt = 0; mt < 2; ++mt)
#pragma unroll
        for (int rh = 0; rh < 2; ++rh) {
            int srow = wm * 32 + mt * 16 + rh * 8 + (lane & 7);
            int scol = wn * 32 + (lane >> 3) * 8;
            uint32_t addr = asb + (uint32_t)(srow * PP + scol) * 2;
            stsm4(addr, vv[mt][0][rh], vv[mt][1][rh], vv[mt][2][rh], vv[mt][3][rh]);
        }
    __syncthreads();
    const __half* Sst = (const __half*)SM;
#pragma unroll
    for (int rr = 0; rr < 16; ++rr) {
        int row = w * 16 + rr;
        long long go = (long long)(by * 128 + row) * SEQ + bx * 64;
        uint32_t val = *(const uint32_t*)(Sst + row * PP + lane * 2);
        *(uint32_t*)(Pz + go + lane * 2) = val;
    }
}

// Fused QKV projection -> fp16 outputs. blockIdx.z selects tensor.
__global__ __launch_bounds__(256)
void gemm_qkv(const __half* __restrict__ xq, const __half* __restrict__ xk,
              const __half* __restrict__ xv,
              const __half* __restrict__ wq, const __half* __restrict__ wk,
              const __half* __restrict__ wv,
              __half* __restrict__ Q, __half* __restrict__ Ko, __half* __restrict__ V)
{
    const __half* A = (blockIdx.z == 0) ? xq : (blockIdx.z == 1) ? xk : xv;
    const __half* B = (blockIdx.z == 0) ? wq : (blockIdx.z == 1) ? wk : wv;
    __half* C = (blockIdx.z == 0) ? Q : (blockIdx.z == 1) ? Ko : V;
    gemm_body<128, 1, false, false>(A, B, nullptr, C, DM, DM, DM, DM, 1.f,
                                    nullptr, nullptr, blockIdx.x, blockIdx.y);
}

// ---------------------------------------------------------------------------
// Fused AV GEMM. P holds fp16 exp values; normalization by 1/sums applied to
// the fp32 attn write (streaming) and to the ctx epilogue.
// ---------------------------------------------------------------------------
__global__ __launch_bounds__(256, 2)
void av_fused(const __half* __restrict__ P, const __half* __restrict__ Vt,
              const float* __restrict__ sums, float* __restrict__ attn,
              __half* __restrict__ ctx)
{
    __shared__ __align__(16) __half Ps[2][128 * 32];
    __shared__ __align__(16) __half Vs[3][64 * 32];
    constexpr uint32_t PSTR = 128 * 32 * 2, VSTR = 64 * 32 * 2;

    const int t = threadIdx.x, lane = t & 31, w = t >> 5;
    const int wm = w & 3, wn = w >> 2, grp = lane >> 2, qid = lane & 3;
    const int h = blockIdx.z, rb = blockIdx.y;

    const int r = t >> 1, hf = t & 1;
    const long long prow = (long long)h * SEQ * SEQ
                         + (long long)(rb * 128 + r) * SEQ + hf * 16;
    const __half* pS = P + prow;
    float* pA = attn + prow;
    const float invr = 1.f / sums[h * SEQ + rb * 128 + r];

    const int lr = t >> 2, ls = t & 3;
    const __half* pV = Vt + (long long)h * DK * SEQ + (long long)lr * SEQ + ls * 8;
    const uint32_t psb = (uint32_t)__cvta_generic_to_shared(&Ps[0][0]);
    const uint32_t vsb = (uint32_t)__cvta_generic_to_shared(&Vs[0][0]);
    const uint32_t dV = swz(lr, ls);
    const uint32_t dP0 = swz(r, 2 * hf), dP1 = swz(r, 2 * hf + 1);

    float acc[2][4][4];
#pragma unroll
    for (int i = 0; i < 2; i++)
#pragma unroll
        for (int j = 0; j < 4; j++)
#pragma unroll
            for (int x = 0; x < 4; x++) acc[i][j][x] = 0.f;

    uint4 sc0, sc1;
    auto ldS = [&](int c) {
        sc0 = *(const uint4*)(pS + c * 32);
        sc1 = *(const uint4*)(pS + c * 32 + 8);
    };
    auto emit = [&](int c, int buf) {
        const __half2* h0 = (const __half2*)&sc0;
        const __half2* h1 = (const __half2*)&sc1;
        float pr[16];
#pragma unroll
        for (int j = 0; j < 4; ++j) {
            float2 f = __half22float2(h0[j]);
            pr[2 * j]     = f.x * invr;
            pr[2 * j + 1] = f.y * invr;
            float2 g = __half22float2(h1[j]);
            pr[8 + 2 * j]     = g.x * invr;
            pr[8 + 2 * j + 1] = g.y * invr;
        }
        float* ap = pA + c * 32;
        __stwt((float4*)(ap),      make_float4(pr[0], pr[1], pr[2], pr[3]));
        __stwt((float4*)(ap + 4),  make_float4(pr[4], pr[5], pr[6], pr[7]));
        __stwt((float4*)(ap + 8),  make_float4(pr[8], pr[9], pr[10], pr[11]));
        __stwt((float4*)(ap + 12), make_float4(pr[12], pr[13], pr[14], pr[15]));
        char* base = (char*)&Ps[buf][0];
        *(uint4*)(base + dP0) = sc0;
        *(uint4*)(base + dP1) = sc1;
    };
    auto cpV = [&](int c, int s) {
        cp16(vsb + s * VSTR + dV, pV + (long long)c * 32);
        cp_commit();
    };

    ldS(0);
    cpV(0, 0); cpV(1, 1);
    emit(0, 0);
    ldS(1);

    for (int c = 0; c < 64; ++c) {
        if (c < 63) cp_wait<1>(); else cp_wait<0>();
        __syncthreads();
        if (c + 2 < 64) cpV(c + 2, (c + 2) % 3);

        const uint32_t pb = psb + (c & 1) * PSTR;
        const uint32_t vb = vsb + (c % 3) * VSTR;
#pragma unroll
        for (int ks = 0; ks < 2; ++ks) {
            uint32_t af[2][4], bf[2][4];
#pragma unroll
            for (int mt = 0; mt < 2; ++mt) {
                int rr = wm * 32 + mt * 16 + (lane & 15);
                int ss = 2 * ks + (lane >> 4);
                ldsm4(af[mt], pb + swz(rr, ss));
            }
#pragma unroll
            for (int p = 0; p < 2; ++p) {
                int rr = wn * 32 + p * 16 + ((lane >> 4) << 3) + (lane & 7);
                int ss = 2 * ks + ((lane >> 3) & 1);
                ldsm4(bf[p], vb + swz(rr, ss));
            }
#pragma unroll
            for (int mt = 0; mt < 2; ++mt)
#pragma unroll
                for (int j = 0; j < 4; ++j)
                    mma_f16(acc[mt][j], af[mt], bf[j >> 1][2 * (j & 1)],
                            bf[j >> 1][2 * (j & 1) + 1]);
        }

        if (c + 1 < 64) {
            emit(c + 1, (c + 1) & 1);
            if (c + 2 < 64) ldS(c + 2);
        }
    }

    // epilogue: ctx = acc * inv[row]
#pragma unroll
    for (int mt = 0; mt < 2; ++mt) {
        int row0 = rb * 128 + wm * 32 + mt * 16 + grp;
        float i0 = 1.f / sums[h * SEQ + row0];
        float i1 = 1.f / sums[h * SEQ + row0 + 8];
#pragma unroll
        for (int j = 0; j < 4; ++j) {
            int col = h * DK + wn * 32 + j * 8 + 2 * qid;
            __half2 v0 = __floats2half2_rn(acc[mt][j][0] * i0, acc[mt][j][1] * i0);
            __half2 v1 = __floats2half2_rn(acc[mt][j][2] * i1, acc[mt][j][3] * i1);
            *(__half2*)&ctx[(long long)row0 * DM + col] = v0;
            *(__half2*)&ctx[(long long)(row0 + 8) * DM + col] = v1;
        }
    }
}

// ---------------------------------------------------------------------------
// Merged fp32 -> fp16 convert for all 7 operand tensors + sums zeroing.
// Blocks [0,6144): inputs; [6144,10240): weights; [10240,10368): zero sums.
// ---------------------------------------------------------------------------
__global__ void cvt_all(const float* __restrict__ q, const float* __restrict__ k,
                        const float* __restrict__ v, const float* __restrict__ wq,
                        const float* __restrict__ wk, const float* __restrict__ wv,
                        const float* __restrict__ wo,
                        __half* __restrict__ xq, __half* __restrict__ xk,
                        __half* __restrict__ xv, __half* __restrict__ hwq,
                        __half* __restrict__ hwk, __half* __restrict__ hwv,
                        __half* __restrict__ hwo, float* __restrict__ sums)
{
    int b = blockIdx.x;
    if (b >= 10240) {
        sums[(b - 10240) * 256 + threadIdx.x] = 0.f;
        return;
    }
    const float* src; __half* dst; int idx;
    if (b < 6144) {
        int ti = b >> 11, r = b & 2047;
        src = (ti == 0) ? q : (ti == 1) ? k : v;
        dst = (ti == 0) ? xq : (ti == 1) ? xk : xv;
        idx = r * 256 + threadIdx.x;
    } else {
        int bb = b - 6144;
        int ti = bb >> 10, r = bb & 1023;
        src = (ti == 0) ? wq : (ti == 1) ? wk : (ti == 2) ? wv : wo;
        dst = (ti == 0) ? hwq : (ti == 1) ? hwk : (ti == 2) ? hwv : hwo;
        idx = r * 256 + threadIdx.x;
    }
    float4 x = ((const float4*)src)[idx];
    __half2 u = __floats2half2_rn(x.x, x.y);
    __half2 w2 = __floats2half2_rn(x.z, x.w);
    *(uint2*)(dst + 4 * (size_t)idx) = make_uint2(*(uint32_t*)&u, *(uint32_t*)&w2);
}

// ---------------------------------------------------------------------------
// Merged RoPE (blocks [0,4096)) + V transpose (blocks [4096,6144)), fp16 in.
// ---------------------------------------------------------------------------
__global__ void rope_vtrans(const __half* __restrict__ Qp, const __half* __restrict__ Kp,
                            const __half* __restrict__ Vp,
                            __half* __restrict__ Qh, __half* __restrict__ Kh,
                            __half* __restrict__ Vt)
{
    if (blockIdx.x < 4096) {
        int tid = blockIdx.x * 256 + threadIdx.x;
        int i = tid & 31;
        int h = (tid >> 5) & (NH - 1);
        int s = tid >> 9;

        float inv_freq = exp2f(-0.41524101186092029f * (float)i); // log2(10000)/32
        float angle = (float)s * inv_freq;
        float sn, cs;
        sincosf(angle, &sn, &cs);

        long long base = (long long)s * DM + h * DK + i;
        float q1 = __half2float(Qp[base]), q2 = __half2float(Qp[base + 32]);
        Qh[base]      = __float2half_rn(q1 * cs - q2 * sn);
        Qh[base + 32] = __float2half_rn(q2 * cs + q1 * sn);
        float k1 = __half2float(Kp[base]), k2 = __half2float(Kp[base + 32]);
        Kh[base]      = __float2half_rn(k1 * cs - k2 * sn);
        Kh[base + 32] = __float2half_rn(k2 * cs + k1 * sn);
    } else {
        __shared__ __half tile[32][33];
        int bb = blockIdx.x - 4096;
        int c0 = (bb & 31) * 32, s0 = (bb >> 5) * 32;
        int tx = threadIdx.x & 31, ty = threadIdx.x >> 5;   // 32 x 8
#pragma unroll
        for (int kk = 0; kk < 4; ++kk)
            tile[ty + 8 * kk][tx] = Vp[(long long)(s0 + ty + 8 * kk) * DM + c0 + tx];
        __syncthreads();
#pragma unroll
        for (int kk = 0; kk < 4; ++kk) {
            int c = c0 + ty + 8 * kk;
            int s = s0 + tx;
            long long o = (long long)(c >> 6) * DK * SEQ + (long long)(c & 63) * SEQ + s;
            Vt[o] = tile[tx][ty + 8 * kk];
        }
    }
}

// ---------------------------------------------------------------------------
extern "C" void kernel_launch(void* const* d_in, const int* in_sizes, int n_in,
                              void* d_out, int out_size)
{
    const float* q  = (const float*)d_in[0];
    const float* k  = (const float*)d_in[1];
    const float* v  = (const float*)d_in[2];
    const float* wq = (const float*)d_in[3];
    const float* wk = (const float*)d_in[4];
    const float* wv = (const float*)d_in[5];
    const float* wo = (const float*)d_in[6];
    const float* bo = (const float*)d_in[7];

    float* out  = (float*)d_out;              // [2048, 1024]
    float* attn = out + (size_t)SEQ * DM;     // [16, 2048, 2048]

    float* pSums;
    cudaGetSymbolAddress((void**)&pSums, g_sums);

    __half *xq,*xk,*xv,*hwq,*hwk,*hwv,*hwo,*Qp,*Kp,*Vp,*Qh,*Kh,*Vt,*P,*ctx;
    cudaGetSymbolAddress((void**)&xq, g_xq);
    cudaGetSymbolAddress((void**)&xk, g_xk);
    cudaGetSymbolAddress((void**)&xv, g_xv);
    cudaGetSymbolAddress((void**)&hwq, g_wq);
    cudaGetSymbolAddress((void**)&hwk, g_wk);
    cudaGetSymbolAddress((void**)&hwv, g_wv);
    cudaGetSymbolAddress((void**)&hwo, g_wo);
    cudaGetSymbolAddress((void**)&Qp, g_Qp);
    cudaGetSymbolAddress((void**)&Kp, g_Kp);
    cudaGetSymbolAddress((void**)&Vp, g_Vp);
    cudaGetSymbolAddress((void**)&Qh, g_Qh);
    cudaGetSymbolAddress((void**)&Kh, g_Kh);
    cudaGetSymbolAddress((void**)&Vt, g_Vt);
    cudaGetSymbolAddress((void**)&P, g_P);
    cudaGetSymbolAddress((void**)&ctx, g_ctx);

    // 0) convert all operands to fp16 + zero row sums (one launch)
    cvt_all<<<10368, 256>>>(q, k, v, wq, wk, wv, wo,
                            xq, xk, xv, hwq, hwk, hwv, hwo, pSums);

    // 1) Fused QKV projections -> fp16 (one launch, 384 CTAs)
    gemm_qkv<<<dim3(DM / 128, SEQ / 128, 3), 256>>>(xq, xk, xv, hwq, hwk, hwv,
                                                    Qp, Kp, Vp);

    // 2) RoPE -> fp16 Q/K ; V transpose -> fp16 Vt (one launch)
    rope_vtrans<<<4096 + 2048, 256>>>(Qp, Kp, Vp, Qh, Kh, Vt);

    // 3) Scores -> fp16 P = exp(QK^T/8 - 8), + row sums (single-shot K=64)
    scores_h<<<dim3(SEQ / 64, SEQ / 128, NH), 256>>>(Qh, Kh, P, pSums);

    // 4) Fused AV: attn = P * inv (streamed fp32), ctx = (P@V) * inv (fp16)
    av_fused<<<dim3(1, SEQ / 128, NH), 256>>>(P, Vt, pSums, attn, ctx);

    // 5) out = ctx @ w_o^T + b_o
    dim3 gOut(DM / 128, SEQ / 128, 1);
    gemm_h<128, 0, true, false><<<gOut, 256>>>(ctx, hwo, out, nullptr, nullptr,
                                               DM, DM, DM, DM, 1.f, bo, 0, 0, 0);
}

// round 17
// speedup vs baseline: 1.0503x; 1.0092x over previous
#include <cuda_runtime.h>
#include <cuda_fp16.h>
#include <cstdint>
#include <math.h>

#define SEQ 2048
#define DM  1024
#define NH  16
#define DK  64

// ---------------- scratch (device globals; no allocation allowed) ----------
__device__ float g_sums[NH * SEQ];
__device__ __half g_xq[SEQ * DM], g_xk[SEQ * DM], g_xv[SEQ * DM];
__device__ __half g_wq[DM * DM], g_wk[DM * DM], g_wv[DM * DM], g_wo[DM * DM];
__device__ __half g_Qp[SEQ * DM], g_Kp[SEQ * DM], g_Vp[SEQ * DM];   // proj out
__device__ __half g_Qh[SEQ * DM], g_Kh[SEQ * DM];   // post-RoPE, packed [h][s][64]
__device__ __half g_Vt[NH * DK * SEQ];
__device__ __half g_P[(size_t)NH * SEQ * SEQ];   // fp16 exp(s-8) values
__device__ __half g_ctx[SEQ * DM];

#define L2E 1.442695041f
#define SHFT (-11.541560327f)   /* -8 * log2(e) */

// ---------------------------------------------------------------------------
__device__ __forceinline__ void ldsm4(uint32_t* r, uint32_t a) {
    asm volatile("ldmatrix.sync.aligned.m8n8.x4.shared.b16 {%0,%1,%2,%3}, [%4];"
        : "=r"(r[0]), "=r"(r[1]), "=r"(r[2]), "=r"(r[3]) : "r"(a));
}
__device__ __forceinline__ void stsm4(uint32_t a, uint32_t r0, uint32_t r1,
                                      uint32_t r2, uint32_t r3) {
    asm volatile("stmatrix.sync.aligned.m8n8.x4.shared.b16 [%0], {%1,%2,%3,%4};"
        :: "r"(a), "r"(r0), "r"(r1), "r"(r2), "r"(r3) : "memory");
}
__device__ __forceinline__ void mma_f16(float* c, const uint32_t* a,
                                        uint32_t b0, uint32_t b1) {
    asm volatile("mma.sync.aligned.m16n8k16.row.col.f32.f16.f16.f32 "
        "{%0,%1,%2,%3},{%4,%5,%6,%7},{%8,%9},{%0,%1,%2,%3};"
        : "+f"(c[0]), "+f"(c[1]), "+f"(c[2]), "+f"(c[3])
        : "r"(a[0]), "r"(a[1]), "r"(a[2]), "r"(a[3]), "r"(b0), "r"(b1));
}
__device__ __forceinline__ void cp16(uint32_t dst, const void* src) {
    asm volatile("cp.async.cg.shared.global [%0], [%1], 16;" :: "r"(dst), "l"(src));
}
__device__ __forceinline__ void cp_commit() {
    asm volatile("cp.async.commit_group;");
}
template<int N> __device__ __forceinline__ void cp_wait() {
    asm volatile("cp.async.wait_group %0;" :: "n"(N));
}
__device__ __forceinline__ uint32_t swz(int r, int s) {
    return (uint32_t)((r * 4 + ((s + (r >> 1)) & 3)) << 4);
}

// ---------------------------------------------------------------------------
// fp16 NT GEMM body. Block tile 128 x TN (64|128), 8 warps (4M x 2N), BK=32,
// 3-stage cp.async.
// EPI=0: fp32 C (+bias), direct stores.
// EPI=1: fp16 Cf via stmatrix-staged, row-coalesced stores (alpha applied).
// ---------------------------------------------------------------------------
template<int TN, int EPI, bool HB>
__device__ __forceinline__ void gemm_body(
    const __half* __restrict__ A, const __half* __restrict__ B,
    float* __restrict__ C, __half* __restrict__ Cf,
    int K, int lda, int ldb, int ldc, float alpha,
    const float* __restrict__ bias, int bx, int by)
{
    constexpr int NP = TN / 32;
    constexpr int NJ = TN / 16;
    constexpr uint32_t ASTR = 128 * 32 * 2, BSTR = TN * 32 * 2;
    __shared__ __align__(16) char SM[3 * ASTR + 3 * BSTR];

    const int t = threadIdx.x, lane = t & 31, w = t >> 5;
    const int wm = w & 3, wn = w >> 2;
    const int grp = lane >> 2, qid = lane & 3;

    const uint32_t asb = (uint32_t)__cvta_generic_to_shared(SM);
    const uint32_t bsb = asb + 3 * ASTR;

    const int lr = t >> 2, ls = t & 3;
    const __half* pA0 = A + (long long)(by * 128 + lr) * lda + ls * 8;
    const __half* pA1 = pA0 + (long long)64 * lda;
    const __half* pB0 = B + (long long)(bx * TN + lr) * ldb + ls * 8;
    const __half* pB1 = pB0 + (long long)64 * ldb;
    const uint32_t dG0 = swz(lr, ls), dG1 = swz(lr + 64, ls);

    auto load_async = [&](int c, int s) {
        cp16(asb + s * ASTR + dG0, pA0 + c * 32);
        cp16(asb + s * ASTR + dG1, pA1 + c * 32);
        cp16(bsb + s * BSTR + dG0, pB0 + c * 32);
        if (TN == 128) cp16(bsb + s * BSTR + dG1, pB1 + c * 32);
    };

    float acc[2][NJ][4];
#pragma unroll
    for (int i = 0; i < 2; i++)
#pragma unroll
        for (int j = 0; j < NJ; j++)
#pragma unroll
            for (int r = 0; r < 4; r++) acc[i][j][r] = 0.f;

    const int NC = K >> 5;
    load_async(0, 0); cp_commit();
    if (NC > 1) { load_async(1, 1); cp_commit(); }

    int s_cur = 0;
    for (int c = 0; c < NC; ++c) {
        if (c + 1 < NC) cp_wait<1>(); else cp_wait<0>();
        __syncthreads();

        if (c + 2 < NC) {
            int s2 = s_cur + 2; if (s2 >= 3) s2 -= 3;
            load_async(c + 2, s2);
            cp_commit();
        }

        const uint32_t ab = asb + s_cur * ASTR;
        const uint32_t bb = bsb + s_cur * BSTR;
#pragma unroll
        for (int ks = 0; ks < 2; ++ks) {
            uint32_t af[2][4], bf[NP][4];
#pragma unroll
            for (int mt = 0; mt < 2; ++mt) {
                int r = wm * 32 + mt * 16 + (lane & 15);
                int s = 2 * ks + (lane >> 4);
                ldsm4(af[mt], ab + swz(r, s));
            }
#pragma unroll
            for (int p = 0; p < NP; ++p) {
                int r = wn * (TN / 2) + p * 16 + ((lane >> 4) << 3) + (lane & 7);
                int s = 2 * ks + ((lane >> 3) & 1);
                ldsm4(bf[p], bb + swz(r, s));
            }
#pragma unroll
            for (int mt = 0; mt < 2; ++mt)
#pragma unroll
                for (int j = 0; j < NJ; ++j)
                    mma_f16(acc[mt][j], af[mt], bf[j >> 1][2 * (j & 1)],
                            bf[j >> 1][2 * (j & 1) + 1]);
        }

        ++s_cur; if (s_cur == 3) s_cur = 0;
        __syncthreads();
    }

    if (EPI == 0) {
#pragma unroll
        for (int mt = 0; mt < 2; ++mt) {
            int row0 = by * 128 + wm * 32 + mt * 16 + grp;
#pragma unroll
            for (int j = 0; j < NJ; ++j) {
                int col = bx * TN + wn * (TN / 2) + j * 8 + 2 * qid;
                float b0 = HB ? bias[col] : 0.f;
                float b1 = HB ? bias[col + 1] : 0.f;
                *(float2*)&C[(long long)row0 * ldc + col] =
                    make_float2(alpha * acc[mt][j][0] + b0, alpha * acc[mt][j][1] + b1);
                *(float2*)&C[(long long)(row0 + 8) * ldc + col] =
                    make_float2(alpha * acc[mt][j][2] + b0, alpha * acc[mt][j][3] + b1);
            }
        }
    } else {
        uint32_t vv[2][NJ][2];
#pragma unroll
        for (int mt = 0; mt < 2; ++mt)
#pragma unroll
            for (int j = 0; j < NJ; ++j) {
                __half2 v0 = __floats2half2_rn(alpha * acc[mt][j][0], alpha * acc[mt][j][1]);
                __half2 v1 = __floats2half2_rn(alpha * acc[mt][j][2], alpha * acc[mt][j][3]);
                vv[mt][j][0] = *(uint32_t*)&v0;
                vv[mt][j][1] = *(uint32_t*)&v1;
            }
        constexpr int PP = TN + 8;
#pragma unroll
        for (int mt = 0; mt < 2; ++mt)
#pragma unroll
            for (int rh = 0; rh < 2; ++rh)
#pragma unroll
                for (int jg = 0; jg < NJ / 4; ++jg) {
                    int srow = wm * 32 + mt * 16 + rh * 8 + (lane & 7);
                    int scol = wn * (TN / 2) + (jg * 4 + (lane >> 3)) * 8;
                    uint32_t addr = asb + (uint32_t)(srow * PP + scol) * 2;
                    stsm4(addr, vv[mt][jg * 4 + 0][rh], vv[mt][jg * 4 + 1][rh],
                          vv[mt][jg * 4 + 2][rh], vv[mt][jg * 4 + 3][rh]);
                }
        __syncthreads();
        const __half* Sst = (const __half*)SM;
#pragma unroll
        for (int rr = 0; rr < 16; ++rr) {
            int row = w * 16 + rr;
            long long go = (long long)(by * 128 + row) * ldc + bx * TN;
            if (TN == 64) {
                uint32_t val = *(const uint32_t*)(Sst + row * PP + lane * 2);
                *(uint32_t*)(Cf + go + lane * 2) = val;
            } else {
                uint2 val = *(const uint2*)(Sst + row * PP + lane * 4);
                *(uint2*)(Cf + go + lane * 4) = val;
            }
        }
    }
}

template<int TN, int EPI, bool HB>
__global__ __launch_bounds__(256)
void gemm_h(const __half* __restrict__ A, const __half* __restrict__ B,
            float* __restrict__ C, __half* __restrict__ Cf,
            int K, int lda, int ldb, int ldc, float alpha,
            const float* __restrict__ bias)
{
    gemm_body<TN, EPI, HB>(A, B, C, Cf, K, lda, ldb, ldc, alpha, bias,
                           blockIdx.x, blockIdx.y);
}

// ---------------------------------------------------------------------------
// Dedicated scores kernel: single-shot K=64, 128x64 tile. Q/K in PACKED
// per-head layout [h][2048][64] -> dense 128B row loads.
// exp epilogue + row sums + staged coalesced stores. occ-3.
// ---------------------------------------------------------------------------
__global__ __launch_bounds__(256, 3)
void scores_h(const __half* __restrict__ Qh, const __half* __restrict__ Kh,
              __half* __restrict__ P, float* __restrict__ sums)
{
    __shared__ __align__(16) char SM[(128 + 64) * 128];   // A 16KB + B 8KB
    const int t = threadIdx.x, lane = t & 31, w = t >> 5;
    const int wm = w & 3, wn = w >> 2, grp = lane >> 2, qid = lane & 3;
    const int bx = blockIdx.x, by = blockIdx.y, h = blockIdx.z;

    const uint32_t asb = (uint32_t)__cvta_generic_to_shared(SM);
    const uint32_t bsb = asb + 128 * 128;

    const __half* Qz = Qh + (long long)h * SEQ * DK;
    const __half* Kz = Kh + (long long)h * SEQ * DK;

    // dense packed rows: row r = 64 halfs = 128B
#pragma unroll
    for (int i = 0; i < 4; ++i) {
        int idx = t + i * 256;
        int r = idx >> 3, s = idx & 7;
        cp16(asb + (uint32_t)(r * 128 + ((s ^ (r & 7)) << 4)),
             Qz + (long long)(by * 128 + r) * DK + s * 8);
    }
#pragma unroll
    for (int i = 0; i < 2; ++i) {
        int idx = t + i * 256;
        int r = idx >> 3, s = idx & 7;
        cp16(bsb + (uint32_t)(r * 128 + ((s ^ (r & 7)) << 4)),
             Kz + (long long)(bx * 64 + r) * DK + s * 8);
    }
    cp_commit();
    cp_wait<0>();
    __syncthreads();

    float acc[2][4][4];
#pragma unroll
    for (int i = 0; i < 2; i++)
#pragma unroll
        for (int j = 0; j < 4; j++)
#pragma unroll
            for (int r = 0; r < 4; r++) acc[i][j][r] = 0.f;

#pragma unroll
    for (int ks = 0; ks < 4; ++ks) {
        uint32_t af[2][4], bf[2][4];
#pragma unroll
        for (int mt = 0; mt < 2; ++mt) {
            int r = wm * 32 + mt * 16 + (lane & 15);
            int s = 2 * ks + (lane >> 4);
            ldsm4(af[mt], asb + (uint32_t)(r * 128 + ((s ^ (r & 7)) << 4)));
        }
#pragma unroll
        for (int p = 0; p < 2; ++p) {
            int r = wn * 32 + p * 16 + ((lane >> 4) << 3) + (lane & 7);
            int s = 2 * ks + ((lane >> 3) & 1);
            ldsm4(bf[p], bsb + (uint32_t)(r * 128 + ((s ^ (r & 7)) << 4)));
        }
#pragma unroll
        for (int mt = 0; mt < 2; ++mt)
#pragma unroll
            for (int j = 0; j < 4; ++j)
                mma_f16(acc[mt][j], af[mt], bf[j >> 1][2 * (j & 1)],
                        bf[j >> 1][2 * (j & 1) + 1]);
    }
    __syncthreads();

    // ---- exp epilogue + row sums + staged stores ----
    float* sz = sums + h * SEQ;
    __half* Pz = P + (long long)h * SEQ * SEQ;
    uint32_t vv[2][4][2];
#pragma unroll
    for (int mt = 0; mt < 2; ++mt) {
        float ps0 = 0.f, ps1 = 0.f;
#pragma unroll
        for (int j = 0; j < 4; ++j) {
            float a0 = 0.125f * acc[mt][j][0], a1 = 0.125f * acc[mt][j][1];
            float a2 = 0.125f * acc[mt][j][2], a3 = 0.125f * acc[mt][j][3];
            __half2 v0 = __floats2half2_rn(exp2f(fmaf(a0, L2E, SHFT)),
                                           exp2f(fmaf(a1, L2E, SHFT)));
            __half2 v1 = __floats2half2_rn(exp2f(fmaf(a2, L2E, SHFT)),
                                           exp2f(fmaf(a3, L2E, SHFT)));
            float2 f0 = __half22float2(v0);
            float2 f1 = __half22float2(v1);
            ps0 += f0.x + f0.y;
            ps1 += f1.x + f1.y;
            vv[mt][j][0] = *(uint32_t*)&v0;
            vv[mt][j][1] = *(uint32_t*)&v1;
        }
        ps0 += __shfl_xor_sync(0xffffffffu, ps0, 1);
        ps0 += __shfl_xor_sync(0xffffffffu, ps0, 2);
        ps1 += __shfl_xor_sync(0xffffffffu, ps1, 1);
        ps1 += __shfl_xor_sync(0xffffffffu, ps1, 2);
        int row0 = by * 128 + wm * 32 + mt * 16 + grp;
        if (qid == 0) {
            atomicAdd(&sz[row0], ps0);
            atomicAdd(&sz[row0 + 8], ps1);
        }
    }
    constexpr int PP = 72;
#pragma unroll
    for (int mt = 0; mt < 2; ++mt)
#pragma unroll
        for (int rh = 0; rh < 2; ++rh) {
            int srow = wm * 32 + mt * 16 + rh * 8 + (lane & 7);
            int scol = wn * 32 + (lane >> 3) * 8;
            uint32_t addr = asb + (uint32_t)(srow * PP + scol) * 2;
            stsm4(addr, vv[mt][0][rh], vv[mt][1][rh], vv[mt][2][rh], vv[mt][3][rh]);
        }
    __syncthreads();
    const __half* Sst = (const __half*)SM;
#pragma unroll
    for (int rr = 0; rr < 16; ++rr) {
        int row = w * 16 + rr;
        long long go = (long long)(by * 128 + row) * SEQ + bx * 64;
        uint32_t val = *(const uint32_t*)(Sst + row * PP + lane * 2);
        *(uint32_t*)(Pz + go + lane * 2) = val;
    }
}

// Fused QKV projection -> fp16 outputs. blockIdx.z selects tensor.
__global__ __launch_bounds__(256)
void gemm_qkv(const __half* __restrict__ xq, const __half* __restrict__ xk,
              const __half* __restrict__ xv,
              const __half* __restrict__ wq, const __half* __restrict__ wk,
              const __half* __restrict__ wv,
              __half* __restrict__ Q, __half* __restrict__ Ko, __half* __restrict__ V)
{
    const __half* A = (blockIdx.z == 0) ? xq : (blockIdx.z == 1) ? xk : xv;
    const __half* B = (blockIdx.z == 0) ? wq : (blockIdx.z == 1) ? wk : wv;
    __half* C = (blockIdx.z == 0) ? Q : (blockIdx.z == 1) ? Ko : V;
    gemm_body<128, 1, false>(A, B, nullptr, C, DM, DM, DM, DM, 1.f,
                             nullptr, blockIdx.x, blockIdx.y);
}

// ---------------------------------------------------------------------------
// Fused AV GEMM. P holds fp16 exp values; normalization by 1/sums applied to
// the fp32 attn write (streaming) and to the ctx epilogue.
// ---------------------------------------------------------------------------
__global__ __launch_bounds__(256, 2)
void av_fused(const __half* __restrict__ P, const __half* __restrict__ Vt,
              const float* __restrict__ sums, float* __restrict__ attn,
              __half* __restrict__ ctx)
{
    __shared__ __align__(16) __half Ps[2][128 * 32];
    __shared__ __align__(16) __half Vs[3][64 * 32];
    constexpr uint32_t PSTR = 128 * 32 * 2, VSTR = 64 * 32 * 2;

    const int t = threadIdx.x, lane = t & 31, w = t >> 5;
    const int wm = w & 3, wn = w >> 2, grp = lane >> 2, qid = lane & 3;
    const int h = blockIdx.z, rb = blockIdx.y;

    const int r = t >> 1, hf = t & 1;
    const long long prow = (long long)h * SEQ * SEQ
                         + (long long)(rb * 128 + r) * SEQ + hf * 16;
    const __half* pS = P + prow;
    float* pA = attn + prow;
    const float invr = 1.f / sums[h * SEQ + rb * 128 + r];

    const int lr = t >> 2, ls = t & 3;
    const __half* pV = Vt + (long long)h * DK * SEQ + (long long)lr * SEQ + ls * 8;
    const uint32_t psb = (uint32_t)__cvta_generic_to_shared(&Ps[0][0]);
    const uint32_t vsb = (uint32_t)__cvta_generic_to_shared(&Vs[0][0]);
    const uint32_t dV = swz(lr, ls);
    const uint32_t dP0 = swz(r, 2 * hf), dP1 = swz(r, 2 * hf + 1);

    float acc[2][4][4];
#pragma unroll
    for (int i = 0; i < 2; i++)
#pragma unroll
        for (int j = 0; j < 4; j++)
#pragma unroll
            for (int x = 0; x < 4; x++) acc[i][j][x] = 0.f;

    uint4 sc0, sc1;
    auto ldS = [&](int c) {
        sc0 = *(const uint4*)(pS + c * 32);
        sc1 = *(const uint4*)(pS + c * 32 + 8);
    };
    auto emit = [&](int c, int buf) {
        const __half2* h0 = (const __half2*)&sc0;
        const __half2* h1 = (const __half2*)&sc1;
        float pr[16];
#pragma unroll
        for (int j = 0; j < 4; ++j) {
            float2 f = __half22float2(h0[j]);
            pr[2 * j]     = f.x * invr;
            pr[2 * j + 1] = f.y * invr;
            float2 g = __half22float2(h1[j]);
            pr[8 + 2 * j]     = g.x * invr;
            pr[8 + 2 * j + 1] = g.y * invr;
        }
        float* ap = pA + c * 32;
        __stwt((float4*)(ap),      make_float4(pr[0], pr[1], pr[2], pr[3]));
        __stwt((float4*)(ap + 4),  make_float4(pr[4], pr[5], pr[6], pr[7]));
        __stwt((float4*)(ap + 8),  make_float4(pr[8], pr[9], pr[10], pr[11]));
        __stwt((float4*)(ap + 12), make_float4(pr[12], pr[13], pr[14], pr[15]));
        char* base = (char*)&Ps[buf][0];
        *(uint4*)(base + dP0) = sc0;
        *(uint4*)(base + dP1) = sc1;
    };
    auto cpV = [&](int c, int s) {
        cp16(vsb + s * VSTR + dV, pV + (long long)c * 32);
        cp_commit();
    };

    ldS(0);
    cpV(0, 0); cpV(1, 1);
    emit(0, 0);
    ldS(1);

    for (int c = 0; c < 64; ++c) {
        if (c < 63) cp_wait<1>(); else cp_wait<0>();
        __syncthreads();
        if (c + 2 < 64) cpV(c + 2, (c + 2) % 3);

        const uint32_t pb = psb + (c & 1) * PSTR;
        const uint32_t vb = vsb + (c % 3) * VSTR;
#pragma unroll
        for (int ks = 0; ks < 2; ++ks) {
            uint32_t af[2][4], bf[2][4];
#pragma unroll
            for (int mt = 0; mt < 2; ++mt) {
                int rr = wm * 32 + mt * 16 + (lane & 15);
                int ss = 2 * ks + (lane >> 4);
                ldsm4(af[mt], pb + swz(rr, ss));
            }
#pragma unroll
            for (int p = 0; p < 2; ++p) {
                int rr = wn * 32 + p * 16 + ((lane >> 4) << 3) + (lane & 7);
                int ss = 2 * ks + ((lane >> 3) & 1);
                ldsm4(bf[p], vb + swz(rr, ss));
            }
#pragma unroll
            for (int mt = 0; mt < 2; ++mt)
#pragma unroll
                for (int j = 0; j < 4; ++j)
                    mma_f16(acc[mt][j], af[mt], bf[j >> 1][2 * (j & 1)],
                            bf[j >> 1][2 * (j & 1) + 1]);
        }

        if (c + 1 < 64) {
            emit(c + 1, (c + 1) & 1);
            if (c + 2 < 64) ldS(c + 2);
        }
    }

    // epilogue: ctx = acc * inv[row]
#pragma unroll
    for (int mt = 0; mt < 2; ++mt) {
        int row0 = rb * 128 + wm * 32 + mt * 16 + grp;
        float i0 = 1.f / sums[h * SEQ + row0];
        float i1 = 1.f / sums[h * SEQ + row0 + 8];
#pragma unroll
        for (int j = 0; j < 4; ++j) {
            int col = h * DK + wn * 32 + j * 8 + 2 * qid;
            __half2 v0 = __floats2half2_rn(acc[mt][j][0] * i0, acc[mt][j][1] * i0);
            __half2 v1 = __floats2half2_rn(acc[mt][j][2] * i1, acc[mt][j][3] * i1);
            *(__half2*)&ctx[(long long)row0 * DM + col] = v0;
            *(__half2*)&ctx[(long long)(row0 + 8) * DM + col] = v1;
        }
    }
}

// ---------------------------------------------------------------------------
// Merged fp32 -> fp16 convert for all 7 operand tensors + sums zeroing.
// ---------------------------------------------------------------------------
__global__ void cvt_all(const float* __restrict__ q, const float* __restrict__ k,
                        const float* __restrict__ v, const float* __restrict__ wq,
                        const float* __restrict__ wk, const float* __restrict__ wv,
                        const float* __restrict__ wo,
                        __half* __restrict__ xq, __half* __restrict__ xk,
                        __half* __restrict__ xv, __half* __restrict__ hwq,
                        __half* __restrict__ hwk, __half* __restrict__ hwv,
                        __half* __restrict__ hwo, float* __restrict__ sums)
{
    int b = blockIdx.x;
    if (b >= 10240) {
        sums[(b - 10240) * 256 + threadIdx.x] = 0.f;
        return;
    }
    const float* src; __half* dst; int idx;
    if (b < 6144) {
        int ti = b >> 11, r = b & 2047;
        src = (ti == 0) ? q : (ti == 1) ? k : v;
        dst = (ti == 0) ? xq : (ti == 1) ? xk : xv;
        idx = r * 256 + threadIdx.x;
    } else {
        int bb = b - 6144;
        int ti = bb >> 10, r = bb & 1023;
        src = (ti == 0) ? wq : (ti == 1) ? wk : (ti == 2) ? wv : wo;
        dst = (ti == 0) ? hwq : (ti == 1) ? hwk : (ti == 2) ? hwv : hwo;
        idx = r * 256 + threadIdx.x;
    }
    float4 x = ((const float4*)src)[idx];
    __half2 u = __floats2half2_rn(x.x, x.y);
    __half2 w2 = __floats2half2_rn(x.z, x.w);
    *(uint2*)(dst + 4 * (size_t)idx) = make_uint2(*(uint32_t*)&u, *(uint32_t*)&w2);
}

// ---------------------------------------------------------------------------
// Merged RoPE (blocks [0,4096)) + V transpose (blocks [4096,6144)), fp16 in.
// RoPE writes PACKED per-head Q/K: [h][s][64].
// ---------------------------------------------------------------------------
__global__ void rope_vtrans(const __half* __restrict__ Qp, const __half* __restrict__ Kp,
                            const __half* __restrict__ Vp,
                            __half* __restrict__ Qh, __half* __restrict__ Kh,
                            __half* __restrict__ Vt)
{
    if (blockIdx.x < 4096) {
        int tid = blockIdx.x * 256 + threadIdx.x;
        int i = tid & 31;
        int h = (tid >> 5) & (NH - 1);
        int s = tid >> 9;

        float inv_freq = exp2f(-0.41524101186092029f * (float)i); // log2(10000)/32
        float angle = (float)s * inv_freq;
        float sn, cs;
        sincosf(angle, &sn, &cs);

        long long base = (long long)s * DM + h * DK + i;
        long long pbase = (long long)h * SEQ * DK + (long long)s * DK + i;
        float q1 = __half2float(Qp[base]), q2 = __half2float(Qp[base + 32]);
        Qh[pbase]      = __float2half_rn(q1 * cs - q2 * sn);
        Qh[pbase + 32] = __float2half_rn(q2 * cs + q1 * sn);
        float k1 = __half2float(Kp[base]), k2 = __half2float(Kp[base + 32]);
        Kh[pbase]      = __float2half_rn(k1 * cs - k2 * sn);
        Kh[pbase + 32] = __float2half_rn(k2 * cs + k1 * sn);
    } else {
        __shared__ __half tile[32][33];
        int bb = blockIdx.x - 4096;
        int c0 = (bb & 31) * 32, s0 = (bb >> 5) * 32;
        int tx = threadIdx.x & 31, ty = threadIdx.x >> 5;   // 32 x 8
#pragma unroll
        for (int kk = 0; kk < 4; ++kk)
            tile[ty + 8 * kk][tx] = Vp[(long long)(s0 + ty + 8 * kk) * DM + c0 + tx];
        __syncthreads();
#pragma unroll
        for (int kk = 0; kk < 4; ++kk) {
            int c = c0 + ty + 8 * kk;
            int s = s0 + tx;
            long long o = (long long)(c >> 6) * DK * SEQ + (long long)(c & 63) * SEQ + s;
            Vt[o] = tile[tx][ty + 8 * kk];
        }
    }
}

// ---------------------------------------------------------------------------
extern "C" void kernel_launch(void* const* d_in, const int* in_sizes, int n_in,
                              void* d_out, int out_size)
{
    const float* q  = (const float*)d_in[0];
    const float* k  = (const float*)d_in[1];
    const float* v  = (const float*)d_in[2];
    const float* wq = (const float*)d_in[3];
    const float* wk = (const float*)d_in[4];
    const float* wv = (const float*)d_in[5];
    const float* wo = (const float*)d_in[6];
    const float* bo = (const float*)d_in[7];

    float* out  = (float*)d_out;              // [2048, 1024]
    float* attn = out + (size_t)SEQ * DM;     // [16, 2048, 2048]

    float* pSums;
    cudaGetSymbolAddress((void**)&pSums, g_sums);

    __half *xq,*xk,*xv,*hwq,*hwk,*hwv,*hwo,*Qp,*Kp,*Vp,*Qh,*Kh,*Vt,*P,*ctx;
    cudaGetSymbolAddress((void**)&xq, g_xq);
    cudaGetSymbolAddress((void**)&xk, g_xk);
    cudaGetSymbolAddress((void**)&xv, g_xv);
    cudaGetSymbolAddress((void**)&hwq, g_wq);
    cudaGetSymbolAddress((void**)&hwk, g_wk);
    cudaGetSymbolAddress((void**)&hwv, g_wv);
    cudaGetSymbolAddress((void**)&hwo, g_wo);
    cudaGetSymbolAddress((void**)&Qp, g_Qp);
    cudaGetSymbolAddress((void**)&Kp, g_Kp);
    cudaGetSymbolAddress((void**)&Vp, g_Vp);
    cudaGetSymbolAddress((void**)&Qh, g_Qh);
    cudaGetSymbolAddress((void**)&Kh, g_Kh);
    cudaGetSymbolAddress((void**)&Vt, g_Vt);
    cudaGetSymbolAddress((void**)&P, g_P);
    cudaGetSymbolAddress((void**)&ctx, g_ctx);

    // 0) convert all operands to fp16 + zero row sums (one launch)
    cvt_all<<<10368, 256>>>(q, k, v, wq, wk, wv, wo,
                            xq, xk, xv, hwq, hwk, hwv, hwo, pSums);

    // 1) Fused QKV projections -> fp16 (one launch, 384 CTAs)
    gemm_qkv<<<dim3(DM / 128, SEQ / 128, 3), 256>>>(xq, xk, xv, hwq, hwk, hwv,
                                                    Qp, Kp, Vp);

    // 2) RoPE -> packed fp16 Q/K ; V transpose -> fp16 Vt (one launch)
    rope_vtrans<<<4096 + 2048, 256>>>(Qp, Kp, Vp, Qh, Kh, Vt);

    // 3) Scores -> fp16 P = exp(QK^T/8 - 8), + row sums (packed Q/K loads)
    scores_h<<<dim3(SEQ / 64, SEQ / 128, NH), 256>>>(Qh, Kh, P, pSums);

    // 4) Fused AV: attn = P * inv (streamed fp32), ctx = (P@V) * inv (fp16)
    av_fused<<<dim3(1, SEQ / 128, NH), 256>>>(P, Vt, pSums, attn, ctx);

    // 5) out = ctx @ w_o^T + b_o
    dim3 gOut(DM / 128, SEQ / 128, 1);
    gemm_h<128, 0, true><<<gOut, 256>>>(ctx, hwo, out, nullptr, DM, DM, DM, DM,
                                        1.f, bo);
}